// round 4
// baseline (speedup 1.0000x reference)
#include <cuda_runtime.h>
#include <math.h>
#include <stdint.h>
#include <stddef.h>

#define BB 64
#define WW 64
#define NN 8192
#define MODES 16
#define J2 32
#define NT 128
#define TBC (NN / NT)
#define SSTR 132
#define WSTR 72

typedef unsigned long long ull;

__device__ float g_hA[(size_t)BB * WW * NN];
__device__ float g_hB[(size_t)BB * WW * NN];
__device__ float g_basis[(size_t)J2 * NN];            // [j][n]
__device__ float g_pF[(size_t)BB * TBC * J2 * WW];    // [b][chunk][j][c]
__device__ float g_Gp[(size_t)BB * WW * J2];          // [b][o][j]

// ---- packed f32x2 helpers ---------------------------------------------------
__device__ __forceinline__ ull ffma2(ull a, ull b, ull c) {
    ull d; asm("fma.rn.f32x2 %0, %1, %2, %3;" : "=l"(d) : "l"(a), "l"(b), "l"(c));
    return d;
}
__device__ __forceinline__ ull pack2(float x, float y) {
    ull d; asm("mov.b64 %0, {%1, %2};" : "=l"(d) : "f"(x), "f"(y));
    return d;
}
__device__ __forceinline__ ull pdup(float x) { return pack2(x, x); }
__device__ __forceinline__ void unpack2(ull v, float& x, float& y) {
    asm("mov.b64 {%0, %1}, %2;" : "=f"(x), "=f"(y) : "l"(v));
}

__global__ void basis_kernel() {
    int n = blockIdx.x * 256 + threadIdx.x;
    if (n >= NN) return;
#pragma unroll
    for (int m = 0; m < MODES; m++) {
        int r = (m * n) & (NN - 1);
        float tf = 2.0f * (float)r / (float)NN;
        float s, c;
        sincospif(tf, &s, &c);
        g_basis[(size_t)(2 * m) * NN + n] = c;
        g_basis[(size_t)(2 * m + 1) * NN + n] = s;
    }
}

__device__ __forceinline__ float gelu_exact(float v) {
    return 0.5f * v * (1.0f + erff(v * 0.70710678118654752f));
}

// dir==0: read g_hA write g_hB ; dir==1: read g_hB write g_hA
template <bool FIRST, bool GELU, bool DFT>
__global__ __launch_bounds__(256, 2)
void combine_kernel(int dir,
                    const float* __restrict__ cw_l, const float* __restrict__ cb_l,
                    const float* __restrict__ xg,  const float* __restrict__ tg,
                    const float* __restrict__ fc0w, const float* __restrict__ fc0b)
{
    extern __shared__ float sm[];
    float* hs   = sm;                     // 64*SSTR
    float* bas  = hs   + 64 * SSTR;       // 32*128
    float* cwT  = bas  + J2 * NT;         // [c][o] 64*WSTR
    float* gpsT = cwT  + 64 * WSTR;       // [j][o] 32*WSTR
    float* cbs  = gpsT + 32 * WSTR;       // 64
    float* xs   = cbs  + 64;              // 128
    float* ts   = xs   + NT;              // 128
    float* w0s  = ts   + NT;              // 128

    const int tid = threadIdx.x;
    const int b   = blockIdx.y;
    const int n0  = blockIdx.x * NT;

    const float* __restrict__ h_in  = dir ? g_hB : g_hA;
    float* __restrict__       h_out = dir ? g_hA : g_hB;

    if (!FIRST) {
        for (int i = tid; i < 64 * NT; i += 256) {
            int c = i >> 7, n = i & (NT - 1);
            hs[c * SSTR + n] = h_in[((size_t)(b * 64 + c)) * NN + n0 + n];
        }
        for (int i = tid; i < 4096; i += 256) {
            int c = i >> 6, o = i & 63;      // consecutive o -> conflict-free smem write
            cwT[c * WSTR + o] = cw_l[o * 64 + c];
        }
        for (int i = tid; i < 2048; i += 256) {
            int j = i >> 6, o = i & 63;
            gpsT[j * WSTR + o] = g_Gp[(size_t)(b * 64 + o) * 32 + j];
        }
        if (tid < 64) cbs[tid] = cb_l[tid];
    } else {
        for (int i = tid; i < NT; i += 256) {
            xs[i] = xg[(size_t)b * NN + n0 + i];
            ts[i] = tg[(size_t)b * NN + n0 + i];
        }
        if (tid < 128) w0s[tid] = fc0w[tid];
        if (tid < 64)  cbs[tid] = fc0b[tid];
    }
    for (int i = tid; i < J2 * NT; i += 256) {
        int j = i >> 7, n = i & (NT - 1);
        bas[j * NT + n] = g_basis[(size_t)j * NN + n0 + n];
    }
    __syncthreads();

    // phase 1: 8 o-rows x 4 n-cols per thread, packed f32x2 along n
    const int tx = tid & 7;
    const int ty = tid >> 3;
    ull acc[8][2];

    if (FIRST) {
#pragma unroll
        for (int oo = 0; oo < 8; oo++) {
            int o = tx * 8 + oo;
            ull wa = pdup(w0s[o]), wb = pdup(w0s[64 + o]), bv = pdup(cbs[o]);
            ulonglong2 xv = *(const ulonglong2*)&xs[ty * 4];
            ulonglong2 tv = *(const ulonglong2*)&ts[ty * 4];
            acc[oo][0] = ffma2(wa, xv.x, ffma2(wb, tv.x, bv));
            acc[oo][1] = ffma2(wa, xv.y, ffma2(wb, tv.y, bv));
        }
    } else {
#pragma unroll
        for (int oo = 0; oo < 8; oo++) {
            ull bv = pdup(cbs[tx * 8 + oo]);
            acc[oo][0] = bv; acc[oo][1] = bv;
        }
#pragma unroll 4
        for (int c = 0; c < 64; c++) {
            ulonglong2 hv = *(const ulonglong2*)&hs[c * SSTR + ty * 4];
            float4 wA = *(const float4*)&cwT[c * WSTR + tx * 8];
            float4 wB = *(const float4*)&cwT[c * WSTR + tx * 8 + 4];
            ull w0 = pdup(wA.x), w1 = pdup(wA.y), w2 = pdup(wA.z), w3 = pdup(wA.w);
            ull w4 = pdup(wB.x), w5 = pdup(wB.y), w6 = pdup(wB.z), w7 = pdup(wB.w);
            acc[0][0] = ffma2(w0, hv.x, acc[0][0]); acc[0][1] = ffma2(w0, hv.y, acc[0][1]);
            acc[1][0] = ffma2(w1, hv.x, acc[1][0]); acc[1][1] = ffma2(w1, hv.y, acc[1][1]);
            acc[2][0] = ffma2(w2, hv.x, acc[2][0]); acc[2][1] = ffma2(w2, hv.y, acc[2][1]);
            acc[3][0] = ffma2(w3, hv.x, acc[3][0]); acc[3][1] = ffma2(w3, hv.y, acc[3][1]);
            acc[4][0] = ffma2(w4, hv.x, acc[4][0]); acc[4][1] = ffma2(w4, hv.y, acc[4][1]);
            acc[5][0] = ffma2(w5, hv.x, acc[5][0]); acc[5][1] = ffma2(w5, hv.y, acc[5][1]);
            acc[6][0] = ffma2(w6, hv.x, acc[6][0]); acc[6][1] = ffma2(w6, hv.y, acc[6][1]);
            acc[7][0] = ffma2(w7, hv.x, acc[7][0]); acc[7][1] = ffma2(w7, hv.y, acc[7][1]);
        }
#pragma unroll 4
        for (int j = 0; j < 32; j++) {
            ulonglong2 bv = *(const ulonglong2*)&bas[j * NT + ty * 4];
            float4 gA = *(const float4*)&gpsT[j * WSTR + tx * 8];
            float4 gB = *(const float4*)&gpsT[j * WSTR + tx * 8 + 4];
            ull g0 = pdup(gA.x), g1 = pdup(gA.y), g2 = pdup(gA.z), g3 = pdup(gA.w);
            ull g4 = pdup(gB.x), g5 = pdup(gB.y), g6 = pdup(gB.z), g7 = pdup(gB.w);
            acc[0][0] = ffma2(g0, bv.x, acc[0][0]); acc[0][1] = ffma2(g0, bv.y, acc[0][1]);
            acc[1][0] = ffma2(g1, bv.x, acc[1][0]); acc[1][1] = ffma2(g1, bv.y, acc[1][1]);
            acc[2][0] = ffma2(g2, bv.x, acc[2][0]); acc[2][1] = ffma2(g2, bv.y, acc[2][1]);
            acc[3][0] = ffma2(g3, bv.x, acc[3][0]); acc[3][1] = ffma2(g3, bv.y, acc[3][1]);
            acc[4][0] = ffma2(g4, bv.x, acc[4][0]); acc[4][1] = ffma2(g4, bv.y, acc[4][1]);
            acc[5][0] = ffma2(g5, bv.x, acc[5][0]); acc[5][1] = ffma2(g5, bv.y, acc[5][1]);
            acc[6][0] = ffma2(g6, bv.x, acc[6][0]); acc[6][1] = ffma2(g6, bv.y, acc[6][1]);
            acc[7][0] = ffma2(g7, bv.x, acc[7][0]); acc[7][1] = ffma2(g7, bv.y, acc[7][1]);
        }
    }

    if (GELU) {
#pragma unroll
        for (int oo = 0; oo < 8; oo++) {
#pragma unroll
            for (int p = 0; p < 2; p++) {
                float a, bf;
                unpack2(acc[oo][p], a, bf);
                acc[oo][p] = pack2(gelu_exact(a), gelu_exact(bf));
            }
        }
    }

#pragma unroll
    for (int oo = 0; oo < 8; oo++) {
        int o = tx * 8 + oo;
        ulonglong2 v; v.x = acc[oo][0]; v.y = acc[oo][1];
        *(ulonglong2*)&h_out[((size_t)(b * 64 + o)) * NN + n0 + ty * 4] = v;
    }

    if (DFT) {
        __syncthreads();
#pragma unroll
        for (int oo = 0; oo < 8; oo++) {
            int o = tx * 8 + oo;
            ulonglong2 v; v.x = acc[oo][0]; v.y = acc[oo][1];
            *(ulonglong2*)&hs[o * SSTR + ty * 4] = v;
        }
        __syncthreads();

        // phase 2: forward-DFT partials. c = channel, 8 j per thread.
        const int c  = tid & 63;
        const int jg = tid >> 6;
        ull facc[8];
#pragma unroll
        for (int jj = 0; jj < 8; jj++) facc[jj] = 0ull;

        for (int nb = 0; nb < NT / 8; nb++) {
            ulonglong2 h0 = *(const ulonglong2*)&hs[c * SSTR + nb * 8];
            ulonglong2 h1 = *(const ulonglong2*)&hs[c * SSTR + nb * 8 + 4];
#pragma unroll
            for (int jj = 0; jj < 8; jj++) {
                int j = jg * 8 + jj;
                ulonglong2 b0 = *(const ulonglong2*)&bas[j * NT + nb * 8];
                ulonglong2 b1 = *(const ulonglong2*)&bas[j * NT + nb * 8 + 4];
                ull s = facc[jj];
                s = ffma2(h0.x, b0.x, s);
                s = ffma2(h0.y, b0.y, s);
                s = ffma2(h1.x, b1.x, s);
                s = ffma2(h1.y, b1.y, s);
                facc[jj] = s;
            }
        }
        size_t base = ((size_t)b * TBC + blockIdx.x) * J2;
#pragma unroll
        for (int jj = 0; jj < 8; jj++) {
            float lo, hi;
            unpack2(facc[jj], lo, hi);
            g_pF[(base + jg * 8 + jj) * WW + c] = lo + hi;
        }
    }
}

// ---- fused reduce + modemix -------------------------------------------------
// F[b][j][c] = sum_chunk pF;  G=(Fr - i Fs)(wr + i wi);
// Gp[2m]=c_m ReG, Gp[2m+1]=-c_m ImG;  c_0=1/N else 2/N
__global__ __launch_bounds__(256)
void reduce_modemix_kernel(const float* __restrict__ swr,
                           const float* __restrict__ swi) {
    __shared__ float fs[64 * 33];   // [c][j]
    int b = blockIdx.x, tid = threadIdx.x;
    for (int idx = tid; idx < 2048; idx += 256) {
        int j = idx >> 6, c = idx & 63;
        float s = 0.0f;
        const float* p = &g_pF[((size_t)b * TBC) * (J2 * WW) + idx];
#pragma unroll 4
        for (int ch = 0; ch < TBC; ch++) s += p[(size_t)ch * (J2 * WW)];
        fs[c * 33 + j] = s;
    }
    __syncthreads();
    int m = tid & 15, og = tid >> 4;
    float re[4] = {0, 0, 0, 0}, im[4] = {0, 0, 0, 0};
    for (int i = 0; i < 64; i++) {
        float fr = fs[i * 33 + 2 * m];
        float fn = fs[i * 33 + 2 * m + 1];
#pragma unroll
        for (int oo = 0; oo < 4; oo++) {
            int o = og * 4 + oo;
            float wr = swr[(i * 64 + o) * 16 + m];
            float wi = swi[(i * 64 + o) * 16 + m];
            re[oo] = fmaf(fr, wr, fmaf(fn, wi, re[oo]));
            im[oo] = fmaf(fr, wi, fmaf(-fn, wr, im[oo]));
        }
    }
    float cm = (m == 0 ? 1.0f : 2.0f) / (float)NN;
#pragma unroll
    for (int oo = 0; oo < 4; oo++) {
        int o = og * 4 + oo;
        g_Gp[(size_t)(b * 64 + o) * 32 + 2 * m]     =  cm * re[oo];
        g_Gp[(size_t)(b * 64 + o) * 32 + 2 * m + 1] = -cm * im[oo];
    }
}

__global__ __launch_bounds__(256, 2)
void fc12_kernel(const float* __restrict__ w1, const float* __restrict__ b1,
                 const float* __restrict__ w2, const float* __restrict__ b2,
                 float* __restrict__ out) {
    extern __shared__ float sm[];
    float* hs  = sm;                  // 64*SSTR
    float* w1s = hs + 64 * SSTR;      // 64*SSTR
    float* w2s = w1s + 64 * SSTR;     // 128
    float* b1s = w2s + 128;           // 128

    int tid = threadIdx.x, b = blockIdx.y, n0 = blockIdx.x * NT;
    const float* __restrict__ h = g_hA;

    for (int i = tid; i < 64 * NT; i += 256) {
        int c = i >> 7, n = i & (NT - 1);
        hs[c * SSTR + n] = h[((size_t)(b * 64 + c)) * NN + n0 + n];
    }
    for (int i = tid; i < 64 * 128; i += 256) {
        int c = i >> 7, j = i & 127;
        w1s[c * SSTR + j] = w1[i];
    }
    if (tid < 128) { w2s[tid] = w2[tid]; b1s[tid] = b1[tid]; }
    __syncthreads();

    int jg = tid & 7;     // j = jj*8 + jg
    int ng = tid >> 3;    // n = ng*4 .. +3

    ull hacc[16][2];
#pragma unroll
    for (int jj = 0; jj < 16; jj++) {
        ull bv = pdup(b1s[jj * 8 + jg]);
        hacc[jj][0] = bv; hacc[jj][1] = bv;
    }
#pragma unroll 2
    for (int c = 0; c < 64; c++) {
        ulonglong2 hv = *(const ulonglong2*)&hs[c * SSTR + ng * 4];
#pragma unroll
        for (int jj = 0; jj < 16; jj++) {
            ull wv = pdup(w1s[c * SSTR + jj * 8 + jg]);
            hacc[jj][0] = ffma2(wv, hv.x, hacc[jj][0]);
            hacc[jj][1] = ffma2(wv, hv.y, hacc[jj][1]);
        }
    }
    float op[4] = {0, 0, 0, 0};
#pragma unroll
    for (int jj = 0; jj < 16; jj++) {
        float wv = w2s[jj * 8 + jg];
        float a0, a1, a2, a3;
        unpack2(hacc[jj][0], a0, a1);
        unpack2(hacc[jj][1], a2, a3);
        op[0] = fmaf(wv, gelu_exact(a0), op[0]);
        op[1] = fmaf(wv, gelu_exact(a1), op[1]);
        op[2] = fmaf(wv, gelu_exact(a2), op[2]);
        op[3] = fmaf(wv, gelu_exact(a3), op[3]);
    }
#pragma unroll
    for (int ni = 0; ni < 4; ni++) {
        op[ni] += __shfl_down_sync(0xffffffffu, op[ni], 4, 8);
        op[ni] += __shfl_down_sync(0xffffffffu, op[ni], 2, 8);
        op[ni] += __shfl_down_sync(0xffffffffu, op[ni], 1, 8);
    }
    if (jg == 0) {
        float bv = b2[0];
#pragma unroll
        for (int ni = 0; ni < 4; ni++)
            out[(size_t)b * NN + n0 + ng * 4 + ni] = op[ni] + bv;
    }
}

static const int CMB_SMEM = (64 * SSTR + J2 * NT + 64 * WSTR + 32 * WSTR + 64 + 3 * 128) * 4;
static const int FC_SMEM  = (64 * SSTR * 2 + 256) * 4;

extern "C" void kernel_launch(void* const* d_in, const int* in_sizes, int n_in,
                              void* d_out, int out_size) {
    const float* x    = (const float*)d_in[0];
    const float* t    = (const float*)d_in[1];
    const float* fc0w = (const float*)d_in[2];
    const float* fc0b = (const float*)d_in[3];
    const float* swr  = (const float*)d_in[4];
    const float* swi  = (const float*)d_in[5];
    const float* cw   = (const float*)d_in[6];
    const float* cb   = (const float*)d_in[7];
    const float* w1   = (const float*)d_in[8];
    const float* b1   = (const float*)d_in[9];
    const float* w2   = (const float*)d_in[10];
    const float* b2   = (const float*)d_in[11];
    float* out = (float*)d_out;

    cudaFuncSetAttribute(combine_kernel<true,  false, true >, cudaFuncAttributeMaxDynamicSharedMemorySize, CMB_SMEM);
    cudaFuncSetAttribute(combine_kernel<false, true,  true >, cudaFuncAttributeMaxDynamicSharedMemorySize, CMB_SMEM);
    cudaFuncSetAttribute(combine_kernel<false, false, false>, cudaFuncAttributeMaxDynamicSharedMemorySize, CMB_SMEM);
    cudaFuncSetAttribute(fc12_kernel, cudaFuncAttributeMaxDynamicSharedMemorySize, FC_SMEM);

    dim3 g(TBC, BB);
    basis_kernel<<<NN / 256, 256>>>();

    combine_kernel<true, false, true><<<g, 256, CMB_SMEM>>>(1, cw, cb, x, t, fc0w, fc0b);

    const size_t SWL = (size_t)64 * 64 * 16;
    reduce_modemix_kernel<<<BB, 256>>>(swr + 0 * SWL, swi + 0 * SWL);
    combine_kernel<false, true, true><<<g, 256, CMB_SMEM>>>(0, cw + 0 * 4096, cb + 0 * 64, x, t, fc0w, fc0b);

    reduce_modemix_kernel<<<BB, 256>>>(swr + 1 * SWL, swi + 1 * SWL);
    combine_kernel<false, true, true><<<g, 256, CMB_SMEM>>>(1, cw + 1 * 4096, cb + 1 * 64, x, t, fc0w, fc0b);

    reduce_modemix_kernel<<<BB, 256>>>(swr + 2 * SWL, swi + 2 * SWL);
    combine_kernel<false, true, true><<<g, 256, CMB_SMEM>>>(0, cw + 2 * 4096, cb + 2 * 64, x, t, fc0w, fc0b);

    reduce_modemix_kernel<<<BB, 256>>>(swr + 3 * SWL, swi + 3 * SWL);
    combine_kernel<false, false, false><<<g, 256, CMB_SMEM>>>(1, cw + 3 * 4096, cb + 3 * 64, x, t, fc0w, fc0b);

    fc12_kernel<<<g, 256, FC_SMEM>>>(w1, b1, w2, b2, out);
}

// round 7
// speedup vs baseline: 1.9075x; 1.9075x over previous
#include <cuda_runtime.h>
#include <cuda_bf16.h>
#include <math.h>
#include <stdint.h>
#include <stddef.h>

#define BB 64
#define NN 8192
#define MODES 16
#define J2 32
#define NT 128
#define TBC (NN / NT)

typedef __nv_bfloat16 bf16;

// ---------------- device scratch --------------------------------------------
__device__ bf16  g_hH0[(size_t)BB * NN * 64];
__device__ bf16  g_hL0[(size_t)BB * NN * 64];
__device__ bf16  g_hH1[(size_t)BB * NN * 64];
__device__ bf16  g_hL1[(size_t)BB * NN * 64];
__device__ float g_pF[(size_t)BB * TBC * J2 * 64];    // [b][chunk][j][c]
__device__ bf16  g_basA[(size_t)NN * 64];             // [n][jh(32)|jl(32)]  (synthesis A)
__device__ bf16  g_basDH[(size_t)J2 * NN];            // [j][n] hi  (DFT A)
__device__ bf16  g_basDL[(size_t)J2 * NN];            // [j][n] lo
__device__ bf16  g_cwH[4 * 64 * 64];                  // [l][o][c]
__device__ bf16  g_cwL[4 * 64 * 64];
__device__ bf16  g_GpB1[(size_t)BB * 64 * 64];        // [b][o][Gph|Gph]
__device__ bf16  g_GpB2[(size_t)BB * 64 * 64];        // [b][o][Gpl|0]
__device__ bf16  g_w1TH[128 * 64];                    // [j][c]
__device__ bf16  g_w1TL[128 * 64];

// ---------------- helpers ----------------------------------------------------
#define SWZ(x) ((x) ^ (((x) >> 3) & 0x70))

__device__ __forceinline__ uint32_t smem_u32(const void* p) {
    uint32_t a;
    asm("{ .reg .u64 t; cvta.to.shared.u64 t, %1; cvt.u32.u64 %0, t; }" : "=r"(a) : "l"(p));
    return a;
}
__device__ __forceinline__ void ldsm4(uint32_t a, uint32_t* r) {
    asm volatile("ldmatrix.sync.aligned.m8n8.x4.shared.b16 {%0,%1,%2,%3}, [%4];"
                 : "=r"(r[0]), "=r"(r[1]), "=r"(r[2]), "=r"(r[3]) : "r"(a));
}
__device__ __forceinline__ void ldsm4t(uint32_t a, uint32_t* r) {
    asm volatile("ldmatrix.sync.aligned.m8n8.x4.trans.shared.b16 {%0,%1,%2,%3}, [%4];"
                 : "=r"(r[0]), "=r"(r[1]), "=r"(r[2]), "=r"(r[3]) : "r"(a));
}
__device__ __forceinline__ void mma16816(float* d, const uint32_t* a, const uint32_t* b) {
    asm volatile(
        "mma.sync.aligned.m16n8k16.row.col.f32.bf16.bf16.f32 "
        "{%0,%1,%2,%3},{%4,%5,%6,%7},{%8,%9},{%0,%1,%2,%3};"
        : "+f"(d[0]), "+f"(d[1]), "+f"(d[2]), "+f"(d[3])
        : "r"(a[0]), "r"(a[1]), "r"(a[2]), "r"(a[3]), "r"(b[0]), "r"(b[1]));
}
__device__ __forceinline__ float gelu_exact(float v) {
    return 0.5f * v * (1.0f + erff(v * 0.70710678118654752f));
}
__device__ __forceinline__ void split_bf(float v, bf16& h, bf16& l) {
    h = __float2bfloat16(v);
    l = __float2bfloat16(v - __bfloat162float(h));
}
__device__ __forceinline__ uint32_t pack_bf(bf16 a, bf16 b) {
    return (uint32_t)__bfloat16_as_ushort(a) | ((uint32_t)__bfloat16_as_ushort(b) << 16);
}

// ---------------- prep -------------------------------------------------------
__global__ void prep_basis() {
    int n = blockIdx.x * 256 + threadIdx.x;
    if (n >= NN) return;
#pragma unroll
    for (int m = 0; m < MODES; m++) {
        int r = (m * n) & (NN - 1);
        float tf = 2.0f * (float)r / (float)NN;
        float s, c;
        sincospif(tf, &s, &c);
        bf16 h, l;
        split_bf(c, h, l);
        g_basA[(size_t)n * 64 + 2 * m] = h;
        g_basA[(size_t)n * 64 + 32 + 2 * m] = l;
        g_basDH[(size_t)(2 * m) * NN + n] = h;
        g_basDL[(size_t)(2 * m) * NN + n] = l;
        split_bf(s, h, l);
        g_basA[(size_t)n * 64 + 2 * m + 1] = h;
        g_basA[(size_t)n * 64 + 32 + 2 * m + 1] = l;
        g_basDH[(size_t)(2 * m + 1) * NN + n] = h;
        g_basDL[(size_t)(2 * m + 1) * NN + n] = l;
    }
}

__global__ void prep_w(const float* __restrict__ cw, const float* __restrict__ w1) {
    int idx = blockIdx.x * 256 + threadIdx.x;
    if (idx < 4 * 64 * 64) {
        bf16 h, l;
        split_bf(cw[idx], h, l);
        g_cwH[idx] = h; g_cwL[idx] = l;
    } else if (idx < 4 * 64 * 64 + 128 * 64) {
        int i2 = idx - 4 * 64 * 64;
        int c = i2 >> 7, j = i2 & 127;
        bf16 h, l;
        split_bf(w1[c * 128 + j], h, l);
        g_w1TH[j * 64 + c] = h; g_w1TL[j * 64 + c] = l;
    }
}

// ---------------- fc0: h0 = grid @ fc0_w + b ---------------------------------
__global__ __launch_bounds__(256)
void fc0_kernel(const float* __restrict__ xg, const float* __restrict__ tg,
                const float* __restrict__ w0, const float* __restrict__ b0) {
    __shared__ float w0s[128], b0s[64];
    int tid = threadIdx.x, b = blockIdx.y;
    if (tid < 128) w0s[tid] = w0[tid];
    if (tid < 64)  b0s[tid] = b0[tid];
    __syncthreads();
    int n = blockIdx.x * 64 + (tid >> 2);
    int q4 = tid & 3;
    float xv = xg[(size_t)b * NN + n], tv = tg[(size_t)b * NN + n];
    int c0 = q4 * 16;
    uint32_t hw[8], lw[8];
#pragma unroll
    for (int k = 0; k < 8; k++) {
        int c = c0 + 2 * k;
        float v0 = fmaf(w0s[c], xv, fmaf(w0s[64 + c], tv, b0s[c]));
        float v1 = fmaf(w0s[c + 1], xv, fmaf(w0s[64 + c + 1], tv, b0s[c + 1]));
        bf16 h0, l0, h1, l1;
        split_bf(v0, h0, l0);
        split_bf(v1, h1, l1);
        hw[k] = pack_bf(h0, h1);
        lw[k] = pack_bf(l0, l1);
    }
    size_t ro = ((size_t)b * NN + n) * 64 + c0;
    *(uint4*)(g_hH0 + ro)     = make_uint4(hw[0], hw[1], hw[2], hw[3]);
    *(uint4*)(g_hH0 + ro + 8) = make_uint4(hw[4], hw[5], hw[6], hw[7]);
    *(uint4*)(g_hL0 + ro)     = make_uint4(lw[0], lw[1], lw[2], lw[3]);
    *(uint4*)(g_hL0 + ro + 8) = make_uint4(lw[4], lw[5], lw[6], lw[7]);
}

// ---------------- DFT MMA core -----------------------------------------------
// F[32j x 64c] = (basDH+basDL)[j][n] x (vH+vL)[n][c]  (3 split terms)
// vH/vL: [n(128)][c(64)] swizzled; basD: [half(2)][j(32)][n'(64)] swizzled,
// half stride = 4096 bytes.  4 warps: jt=(w&1)*16, cbase=(w>>1)*32.
__device__ __forceinline__ void dft_core(uint32_t sb, int VHo, int VLo, int BHo, int BLo,
                                         int wid, int lane, size_t pfbase) {
    int lr = lane & 7, li = lane >> 3;
    int drA = (li & 1) * 8, dcA = (li >> 1) * 16;
    int jt = (wid & 1) * 16;
    int cb2 = (wid >> 1) * 64;   // byte col base = cbase*2
    float f[4][4];
#pragma unroll
    for (int i = 0; i < 4; i++)
#pragma unroll
        for (int k = 0; k < 4; k++) f[i][k] = 0.0f;

    const int AO2[3] = {BHo, BHo, BLo};
    const int BO2[3] = {VHo, VLo, VHo};
#pragma unroll
    for (int p = 0; p < 3; p++) {
        uint32_t ab = sb + AO2[p], vb = sb + BO2[p];
#pragma unroll
        for (int s = 0; s < 8; s++) {
            int half = s >> 2, kb = (s & 3) * 32;
            uint32_t a[4], b0[4], b1[4];
            ldsm4(ab + half * 4096 + SWZ((jt + drA + lr) * 128 + kb + dcA), a);
            ldsm4t(vb + SWZ((16 * s + drA + lr) * 128 + cb2 + dcA), b0);
            ldsm4t(vb + SWZ((16 * s + drA + lr) * 128 + cb2 + 32 + dcA), b1);
            mma16816(f[0], a, b0); mma16816(f[1], a, b0 + 2);
            mma16816(f[2], a, b1); mma16816(f[3], a, b1 + 2);
        }
    }
    int q = lane & 3, g = lane >> 2;
    int cbase = (wid >> 1) * 32;
#pragma unroll
    for (int nt = 0; nt < 4; nt++) {
        int c = cbase + nt * 8 + 2 * q;
        int j = jt + g;
        *(float2*)&g_pF[(pfbase + j) * 64 + c]     = make_float2(f[nt][0], f[nt][1]);
        *(float2*)&g_pF[(pfbase + j + 8) * 64 + c] = make_float2(f[nt][2], f[nt][3]);
    }
}

// ---------------- standalone DFT of h0 (after fc0) ---------------------------
#define D0_VH 0
#define D0_VL 16384
#define D0_BH 32768
#define D0_BL 40960
#define D0_SZ 49152

__global__ __launch_bounds__(128)
void dft0_kernel() {
    extern __shared__ char smc[];
    uint32_t sb = smem_u32(smc);
    int tid = threadIdx.x, wid = tid >> 5, lane = tid & 31;
    int b = blockIdx.y, n0 = blockIdx.x * NT;
    const bf16* vh = g_hH0 + ((size_t)b * NN + n0) * 64;
    const bf16* vl = g_hL0 + ((size_t)b * NN + n0) * 64;
    for (int i = tid; i < 1024; i += 128) {
        int r = i >> 3, q = i & 7;
        uint32_t so = SWZ(r * 128 + q * 16);
        *(uint4*)(smc + D0_VH + so) = ((const uint4*)(vh + (size_t)r * 64))[q];
        *(uint4*)(smc + D0_VL + so) = ((const uint4*)(vl + (size_t)r * 64))[q];
    }
    for (int i = tid; i < 512; i += 128) {
        int half = i >> 8, rest = i & 255, j = rest >> 3, q = rest & 7;
        uint32_t so = half * 4096 + SWZ(j * 128 + q * 16);
        *(uint4*)(smc + D0_BH + so) = ((const uint4*)(g_basDH + (size_t)j * NN + n0 + half * 64))[q];
        *(uint4*)(smc + D0_BL + so) = ((const uint4*)(g_basDL + (size_t)j * NN + n0 + half * 64))[q];
    }
    __syncthreads();
    dft_core(sb, D0_VH, D0_VL, D0_BH, D0_BL, wid, lane,
             ((size_t)b * TBC + blockIdx.x) * J2);
}

// ---------------- fused reduce + modemix -------------------------------------
__global__ __launch_bounds__(256)
void reduce_modemix_kernel(const float* __restrict__ swr,
                           const float* __restrict__ swi) {
    __shared__ float fs[64 * 33];   // [c][j]
    int b = blockIdx.x, tid = threadIdx.x;
    for (int idx = tid; idx < 2048; idx += 256) {
        int j = idx >> 6, c = idx & 63;
        float s = 0.0f;
        const float* p = &g_pF[((size_t)b * TBC) * (J2 * 64) + idx];
#pragma unroll 4
        for (int ch = 0; ch < TBC; ch++) s += p[(size_t)ch * (J2 * 64)];
        fs[c * 33 + j] = s;
    }
    __syncthreads();
    int m = tid & 15, og = tid >> 4;
    float re[4] = {0, 0, 0, 0}, im[4] = {0, 0, 0, 0};
    for (int i = 0; i < 64; i++) {
        float fr = fs[i * 33 + 2 * m];
        float fn = fs[i * 33 + 2 * m + 1];
#pragma unroll
        for (int oo = 0; oo < 4; oo++) {
            int o = og * 4 + oo;
            float wr = swr[(i * 64 + o) * 16 + m];
            float wi = swi[(i * 64 + o) * 16 + m];
            re[oo] = fmaf(fr, wr, fmaf(fn, wi, re[oo]));
            im[oo] = fmaf(fr, wi, fmaf(-fn, wr, im[oo]));
        }
    }
    float cm = (m == 0 ? 1.0f : 2.0f) / (float)NN;
    bf16 z = __float2bfloat16(0.0f);
#pragma unroll
    for (int oo = 0; oo < 4; oo++) {
        int o = og * 4 + oo;
        float g0 = cm * re[oo];
        float g1 = -cm * im[oo];
        size_t r = ((size_t)b * 64 + o) * 64;
        bf16 h, l;
        split_bf(g0, h, l);
        g_GpB1[r + 2 * m] = h;      g_GpB1[r + 32 + 2 * m] = h;
        g_GpB2[r + 2 * m] = l;      g_GpB2[r + 32 + 2 * m] = z;
        split_bf(g1, h, l);
        g_GpB1[r + 2 * m + 1] = h;  g_GpB1[r + 32 + 2 * m + 1] = h;
        g_GpB2[r + 2 * m + 1] = l;  g_GpB2[r + 32 + 2 * m + 1] = z;
    }
}

// ---------------- fused layer: conv + synthesis (+gelu) (+DFT) ----------------
#define MM_HH 0
#define MM_HL 16384
#define MM_BA 32768
#define MM_WH 49152
#define MM_WL 57344
#define MM_G1 65536
#define MM_G2 73728
#define MM_CB 81920
#define MM_SZ 82432

template <bool GELU, bool DFT>
__global__ __launch_bounds__(128, 2)
void mma_layer(int dir, int layer, const float* __restrict__ cb_all) {
    extern __shared__ char smc[];
    uint32_t sb = smem_u32(smc);
    int tid = threadIdx.x, wid = tid >> 5, lane = tid & 31;
    int b = blockIdx.y, n0 = blockIdx.x * NT;

    const bf16* hHsrc = (dir ? g_hH1 : g_hH0) + ((size_t)b * NN + n0) * 64;
    const bf16* hLsrc = (dir ? g_hL1 : g_hL0) + ((size_t)b * NN + n0) * 64;
    bf16* hHdst = (dir ? g_hH0 : g_hH1) + ((size_t)b * NN + n0) * 64;
    bf16* hLdst = (dir ? g_hL0 : g_hL1) + ((size_t)b * NN + n0) * 64;

    for (int i = tid; i < 1024; i += 128) {
        int r = i >> 3, q = i & 7;
        uint32_t so = SWZ(r * 128 + q * 16);
        *(uint4*)(smc + MM_HH + so) = ((const uint4*)(hHsrc + (size_t)r * 64))[q];
        *(uint4*)(smc + MM_HL + so) = ((const uint4*)(hLsrc + (size_t)r * 64))[q];
        *(uint4*)(smc + MM_BA + so) = ((const uint4*)(g_basA + (size_t)(n0 + r) * 64))[q];
    }
    for (int i = tid; i < 512; i += 128) {
        int r = i >> 3, q = i & 7;
        uint32_t so = SWZ(r * 128 + q * 16);
        *(uint4*)(smc + MM_WH + so) = ((const uint4*)(g_cwH + (size_t)(layer * 64 + r) * 64))[q];
        *(uint4*)(smc + MM_WL + so) = ((const uint4*)(g_cwL + (size_t)(layer * 64 + r) * 64))[q];
        *(uint4*)(smc + MM_G1 + so) = ((const uint4*)(g_GpB1 + ((size_t)b * 64 + r) * 64))[q];
        *(uint4*)(smc + MM_G2 + so) = ((const uint4*)(g_GpB2 + ((size_t)b * 64 + r) * 64))[q];
    }
    if (tid < 64) ((float*)(smc + MM_CB))[tid] = cb_all[layer * 64 + tid];
    __syncthreads();

    // ---- main GEMM: 4 warps, warp = 32 n-rows x 64 o-cols -------------------
    int lr = lane & 7, li = lane >> 3;
    int drA = (li & 1) * 8, dcA = (li >> 1) * 16;
    int drB = (li >> 1) * 8, dcB = (li & 1) * 16;
    int rA0 = 32 * wid;

    float acc[2][8][4];
#pragma unroll
    for (int mt = 0; mt < 2; mt++)
#pragma unroll
        for (int nt = 0; nt < 8; nt++)
#pragma unroll
            for (int k = 0; k < 4; k++) acc[mt][nt][k] = 0.0f;

    const int AO[5] = {MM_HH, MM_HL, MM_HH, MM_BA, MM_BA};
    const int BO[5] = {MM_WH, MM_WH, MM_WL, MM_G1, MM_G2};
#pragma unroll
    for (int p = 0; p < 5; p++) {
        uint32_t ab = sb + AO[p], bbse = sb + BO[p];
#pragma unroll
        for (int s = 0; s < 4; s++) {
            int kb = s * 32;
            uint32_t a0[4], a1[4];
            ldsm4(ab + SWZ((rA0 + drA + lr) * 128 + kb + dcA), a0);
            ldsm4(ab + SWZ((rA0 + 16 + drA + lr) * 128 + kb + dcA), a1);
#pragma unroll
            for (int np = 0; np < 4; np++) {
                uint32_t bb[4];
                ldsm4(bbse + SWZ((np * 16 + drB + lr) * 128 + kb + dcB), bb);
                mma16816(acc[0][2 * np],     a0, bb);
                mma16816(acc[0][2 * np + 1], a0, bb + 2);
                mma16816(acc[1][2 * np],     a1, bb);
                mma16816(acc[1][2 * np + 1], a1, bb + 2);
            }
        }
    }
    __syncthreads();   // all reads of operand smem done

    // ---- epilogue: bias + gelu, write vH/vL into HH/HL regions --------------
    int q = lane & 3, g = lane >> 2;
    const float* cbs = (const float*)(smc + MM_CB);
#pragma unroll
    for (int mt = 0; mt < 2; mt++) {
#pragma unroll
        for (int nt = 0; nt < 8; nt++) {
            int o0 = nt * 8 + 2 * q;
            int r0 = 32 * wid + 16 * mt + g;
            float v0 = acc[mt][nt][0] + cbs[o0];
            float v1 = acc[mt][nt][1] + cbs[o0 + 1];
            float v2 = acc[mt][nt][2] + cbs[o0];
            float v3 = acc[mt][nt][3] + cbs[o0 + 1];
            if (GELU) {
                v0 = gelu_exact(v0); v1 = gelu_exact(v1);
                v2 = gelu_exact(v2); v3 = gelu_exact(v3);
            }
            bf16 h0, l0, h1, l1;
            split_bf(v0, h0, l0); split_bf(v1, h1, l1);
            *(uint32_t*)(smc + MM_HH + SWZ(r0 * 128 + o0 * 2)) = pack_bf(h0, h1);
            *(uint32_t*)(smc + MM_HL + SWZ(r0 * 128 + o0 * 2)) = pack_bf(l0, l1);
            split_bf(v2, h0, l0); split_bf(v3, h1, l1);
            *(uint32_t*)(smc + MM_HH + SWZ((r0 + 8) * 128 + o0 * 2)) = pack_bf(h0, h1);
            *(uint32_t*)(smc + MM_HL + SWZ((r0 + 8) * 128 + o0 * 2)) = pack_bf(l0, l1);
        }
    }
    if (DFT) {
        // basD tiles into (dead) WH/WL regions, half stride 4096
        for (int i = tid; i < 512; i += 128) {
            int half = i >> 8, rest = i & 255, j = rest >> 3, qq = rest & 7;
            uint32_t so = half * 4096 + SWZ(j * 128 + qq * 16);
            *(uint4*)(smc + MM_WH + so) = ((const uint4*)(g_basDH + (size_t)j * NN + n0 + half * 64))[qq];
            *(uint4*)(smc + MM_WL + so) = ((const uint4*)(g_basDL + (size_t)j * NN + n0 + half * 64))[qq];
        }
    }
    __syncthreads();

    // ---- coalesced copy-out of vH/vL to gmem --------------------------------
    for (int i = tid; i < 1024; i += 128) {
        int r = i >> 3, qq = i & 7;
        uint32_t so = SWZ(r * 128 + qq * 16);
        ((uint4*)(hHdst + (size_t)r * 64))[qq] = *(uint4*)(smc + MM_HH + so);
        ((uint4*)(hLdst + (size_t)r * 64))[qq] = *(uint4*)(smc + MM_HL + so);
    }
    if (DFT) {
        dft_core(sb, MM_HH, MM_HL, MM_WH, MM_WL, wid, lane,
                 ((size_t)b * TBC + blockIdx.x) * J2);
    }
}

// ---------------- fc1 + gelu + fc2 via MMA -----------------------------------
#define FC_HH 0
#define FC_HL 16384
#define FC_WH 32768
#define FC_WL 49152
#define FC_B1 65536
#define FC_W2 66048
#define FC_SZ 66560

__global__ __launch_bounds__(256, 2)
void fc12_kernel(const float* __restrict__ b1, const float* __restrict__ w2,
                 const float* __restrict__ b2, float* __restrict__ out) {
    extern __shared__ char smc[];
    uint32_t sb = smem_u32(smc);
    int tid = threadIdx.x, wid = tid >> 5, lane = tid & 31;
    int b = blockIdx.y, n0 = blockIdx.x * NT;

    const bf16* hH = g_hH0 + ((size_t)b * NN + n0) * 64;
    const bf16* hL = g_hL0 + ((size_t)b * NN + n0) * 64;
    for (int i = tid; i < 1024; i += 256) {
        int r = i >> 3, q = i & 7;
        uint32_t so = SWZ(r * 128 + q * 16);
        *(uint4*)(smc + FC_HH + so) = ((const uint4*)(hH + (size_t)r * 64))[q];
        *(uint4*)(smc + FC_HL + so) = ((const uint4*)(hL + (size_t)r * 64))[q];
        *(uint4*)(smc + FC_WH + so) = ((const uint4*)(g_w1TH + (size_t)r * 64))[q];
        *(uint4*)(smc + FC_WL + so) = ((const uint4*)(g_w1TL + (size_t)r * 64))[q];
    }
    if (tid < 128) {
        ((float*)(smc + FC_B1))[tid] = b1[tid];
        ((float*)(smc + FC_W2))[tid] = w2[tid];
    }
    __syncthreads();

    int lr = lane & 7, li = lane >> 3;
    int drA = (li & 1) * 8, dcA = (li >> 1) * 16;
    int drB = (li >> 1) * 8, dcB = (li & 1) * 16;
    int rA0 = 16 * wid;

    float acc[16][4];
#pragma unroll
    for (int nt = 0; nt < 16; nt++)
#pragma unroll
        for (int k = 0; k < 4; k++) acc[nt][k] = 0.0f;

    const int AO[3] = {FC_HH, FC_HL, FC_HH};
    const int BO[3] = {FC_WH, FC_WH, FC_WL};
#pragma unroll
    for (int p = 0; p < 3; p++) {
        uint32_t ab = sb + AO[p], bbse = sb + BO[p];
#pragma unroll
        for (int s = 0; s < 4; s++) {
            int kb = s * 32;
            uint32_t a[4];
            ldsm4(ab + SWZ((rA0 + drA + lr) * 128 + kb + dcA), a);
#pragma unroll
            for (int np = 0; np < 8; np++) {
                uint32_t bb[4];
                ldsm4(bbse + SWZ((np * 16 + drB + lr) * 128 + kb + dcB), bb);
                mma16816(acc[2 * np],     a, bb);
                mma16816(acc[2 * np + 1], a, bb + 2);
            }
        }
    }

    // epilogue: gelu(acc + b1) . w2, reduce over j
    int q = lane & 3, g = lane >> 2;
    const float* b1s = (const float*)(smc + FC_B1);
    const float* w2s = (const float*)(smc + FC_W2);
    float s0 = 0.0f, s1 = 0.0f;
#pragma unroll
    for (int nt = 0; nt < 16; nt++) {
        int j0 = nt * 8 + 2 * q;
        s0 = fmaf(w2s[j0],     gelu_exact(acc[nt][0] + b1s[j0]),     s0);
        s0 = fmaf(w2s[j0 + 1], gelu_exact(acc[nt][1] + b1s[j0 + 1]), s0);
        s1 = fmaf(w2s[j0],     gelu_exact(acc[nt][2] + b1s[j0]),     s1);
        s1 = fmaf(w2s[j0 + 1], gelu_exact(acc[nt][3] + b1s[j0 + 1]), s1);
    }
    s0 += __shfl_xor_sync(0xffffffffu, s0, 1);
    s0 += __shfl_xor_sync(0xffffffffu, s0, 2);
    s1 += __shfl_xor_sync(0xffffffffu, s1, 1);
    s1 += __shfl_xor_sync(0xffffffffu, s1, 2);
    if (q == 0) {
        float bv = b2[0];
        out[(size_t)b * NN + n0 + 16 * wid + g]     = s0 + bv;
        out[(size_t)b * NN + n0 + 16 * wid + g + 8] = s1 + bv;
    }
}

// ---------------- host launcher ----------------------------------------------
extern "C" void kernel_launch(void* const* d_in, const int* in_sizes, int n_in,
                              void* d_out, int out_size) {
    const float* x    = (const float*)d_in[0];
    const float* t    = (const float*)d_in[1];
    const float* fc0w = (const float*)d_in[2];
    const float* fc0b = (const float*)d_in[3];
    const float* swr  = (const float*)d_in[4];
    const float* swi  = (const float*)d_in[5];
    const float* cw   = (const float*)d_in[6];
    const float* cb   = (const float*)d_in[7];
    const float* w1   = (const float*)d_in[8];
    const float* b1   = (const float*)d_in[9];
    const float* w2   = (const float*)d_in[10];
    const float* b2   = (const float*)d_in[11];
    float* out = (float*)d_out;

    cudaFuncSetAttribute(mma_layer<true,  true >, cudaFuncAttributeMaxDynamicSharedMemorySize, MM_SZ);
    cudaFuncSetAttribute(mma_layer<false, false>, cudaFuncAttributeMaxDynamicSharedMemorySize, MM_SZ);
    cudaFuncSetAttribute(dft0_kernel, cudaFuncAttributeMaxDynamicSharedMemorySize, D0_SZ);
    cudaFuncSetAttribute(fc12_kernel, cudaFuncAttributeMaxDynamicSharedMemorySize, FC_SZ);

    dim3 g(TBC, BB);
    prep_basis<<<NN / 256, 256>>>();
    prep_w<<<(4 * 4096 + 128 * 64 + 255) / 256, 256>>>(cw, w1);

    fc0_kernel<<<dim3(NN / 64, BB), 256>>>(x, t, fc0w, fc0b);
    dft0_kernel<<<g, 128, D0_SZ>>>();

    const size_t SWL = (size_t)64 * 64 * 16;
    reduce_modemix_kernel<<<BB, 256>>>(swr + 0 * SWL, swi + 0 * SWL);
    mma_layer<true, true><<<g, 128, MM_SZ>>>(0, 0, cb);

    reduce_modemix_kernel<<<BB, 256>>>(swr + 1 * SWL, swi + 1 * SWL);
    mma_layer<true, true><<<g, 128, MM_SZ>>>(1, 1, cb);

    reduce_modemix_kernel<<<BB, 256>>>(swr + 2 * SWL, swi + 2 * SWL);
    mma_layer<true, true><<<g, 128, MM_SZ>>>(0, 2, cb);

    reduce_modemix_kernel<<<BB, 256>>>(swr + 3 * SWL, swi + 3 * SWL);
    mma_layer<false, false><<<g, 128, MM_SZ>>>(1, 3, cb);

    fc12_kernel<<<g, 256, FC_SZ>>>(b1, w2, b2, out);
}

// round 8
// speedup vs baseline: 2.8685x; 1.5038x over previous
#include <cuda_runtime.h>
#include <cuda_bf16.h>
#include <math.h>
#include <stdint.h>
#include <stddef.h>

#define BB 64
#define NN 8192
#define MODES 16
#define J2 32
#define NT 128
#define TBC (NN / NT)

typedef __nv_bfloat16 bf16;

// ---------------- device scratch --------------------------------------------
__device__ bf16  g_hH0[(size_t)BB * NN * 64];
__device__ bf16  g_hL0[(size_t)BB * NN * 64];
__device__ bf16  g_hH1[(size_t)BB * NN * 64];
__device__ bf16  g_hL1[(size_t)BB * NN * 64];
__device__ float g_pF[(size_t)BB * TBC * J2 * 64];    // [b][chunk][j][c]
__device__ bf16  g_basA[(size_t)NN * 64];             // [n][jh(32)|jl(32)]
__device__ bf16  g_basDH[(size_t)J2 * NN];            // [j][n] hi
__device__ bf16  g_basDL[(size_t)J2 * NN];            // [j][n] lo
__device__ bf16  g_cwH[4 * 64 * 64];                  // [l][o][c]
__device__ bf16  g_cwL[4 * 64 * 64];
__device__ bf16  g_GpB1[(size_t)BB * 64 * 64];        // [b][o][Gph|Gph]
__device__ bf16  g_GpB2[(size_t)BB * 64 * 64];        // [b][o][Gpl|0]
__device__ bf16  g_w1TH[128 * 64];                    // [j][c]
__device__ bf16  g_w1TL[128 * 64];

// ---------------- helpers ----------------------------------------------------
#define SWZ(x) ((x) ^ (((x) >> 3) & 0x70))

__device__ __forceinline__ uint32_t smem_u32(const void* p) {
    uint32_t a;
    asm("{ .reg .u64 t; cvta.to.shared.u64 t, %1; cvt.u32.u64 %0, t; }" : "=r"(a) : "l"(p));
    return a;
}
__device__ __forceinline__ void ldsm4(uint32_t a, uint32_t* r) {
    asm volatile("ldmatrix.sync.aligned.m8n8.x4.shared.b16 {%0,%1,%2,%3}, [%4];"
                 : "=r"(r[0]), "=r"(r[1]), "=r"(r[2]), "=r"(r[3]) : "r"(a));
}
__device__ __forceinline__ void ldsm4t(uint32_t a, uint32_t* r) {
    asm volatile("ldmatrix.sync.aligned.m8n8.x4.trans.shared.b16 {%0,%1,%2,%3}, [%4];"
                 : "=r"(r[0]), "=r"(r[1]), "=r"(r[2]), "=r"(r[3]) : "r"(a));
}
__device__ __forceinline__ void mma16816(float* d, const uint32_t* a, const uint32_t* b) {
    asm volatile(
        "mma.sync.aligned.m16n8k16.row.col.f32.bf16.bf16.f32 "
        "{%0,%1,%2,%3},{%4,%5,%6,%7},{%8,%9},{%0,%1,%2,%3};"
        : "+f"(d[0]), "+f"(d[1]), "+f"(d[2]), "+f"(d[3])
        : "r"(a[0]), "r"(a[1]), "r"(a[2]), "r"(a[3]), "r"(b[0]), "r"(b[1]));
}
__device__ __forceinline__ float gelu_exact(float v) {
    return 0.5f * v * (1.0f + erff(v * 0.70710678118654752f));
}
__device__ __forceinline__ void split_bf(float v, bf16& h, bf16& l) {
    h = __float2bfloat16(v);
    l = __float2bfloat16(v - __bfloat162float(h));
}
__device__ __forceinline__ uint32_t pack_bf(bf16 a, bf16 b) {
    return (uint32_t)__bfloat16_as_ushort(a) | ((uint32_t)__bfloat16_as_ushort(b) << 16);
}

// ---------------- prep -------------------------------------------------------
__global__ void prep_basis() {
    int n = blockIdx.x * 256 + threadIdx.x;
    if (n >= NN) return;
#pragma unroll
    for (int m = 0; m < MODES; m++) {
        int r = (m * n) & (NN - 1);
        float tf = 2.0f * (float)r / (float)NN;
        float s, c;
        sincospif(tf, &s, &c);
        bf16 h, l;
        split_bf(c, h, l);
        g_basA[(size_t)n * 64 + 2 * m] = h;
        g_basA[(size_t)n * 64 + 32 + 2 * m] = l;
        g_basDH[(size_t)(2 * m) * NN + n] = h;
        g_basDL[(size_t)(2 * m) * NN + n] = l;
        split_bf(s, h, l);
        g_basA[(size_t)n * 64 + 2 * m + 1] = h;
        g_basA[(size_t)n * 64 + 32 + 2 * m + 1] = l;
        g_basDH[(size_t)(2 * m + 1) * NN + n] = h;
        g_basDL[(size_t)(2 * m + 1) * NN + n] = l;
    }
}

__global__ void prep_w(const float* __restrict__ cw, const float* __restrict__ w1) {
    int idx = blockIdx.x * 256 + threadIdx.x;
    if (idx < 4 * 64 * 64) {
        bf16 h, l;
        split_bf(cw[idx], h, l);
        g_cwH[idx] = h; g_cwL[idx] = l;
    } else if (idx < 4 * 64 * 64 + 128 * 64) {
        int i2 = idx - 4 * 64 * 64;
        int c = i2 >> 7, j = i2 & 127;
        bf16 h, l;
        split_bf(w1[c * 128 + j], h, l);
        g_w1TH[j * 64 + c] = h; g_w1TL[j * 64 + c] = l;
    }
}

// ---------------- DFT MMA core (8 warps) -------------------------------------
// F[32j x 64c] = (basDH+basDL)[j][n] x (vH+vL)[n][c]  (3 split terms)
// vH/vL: [n(128)][c(64)] swizzled; basD: [half(2)][j(32)][n'(64)] swizzled,
// half stride = 4096 B.  8 warps: jt=(w&1)*16, cbase=(w>>1)*16.
__device__ __forceinline__ void dft_core8(uint32_t sb, int VHo, int VLo, int BHo, int BLo,
                                          int wid, int lane, size_t pfbase) {
    int lr = lane & 7, li = lane >> 3;
    int drA = (li & 1) * 8, dcA = (li >> 1) * 16;
    int jt = (wid & 1) * 16;
    int cb2 = (wid >> 1) * 32;   // byte col base
    float f[2][4];
#pragma unroll
    for (int i = 0; i < 2; i++)
#pragma unroll
        for (int k = 0; k < 4; k++) f[i][k] = 0.0f;

    const int AO2[3] = {BHo, BHo, BLo};
    const int BO2[3] = {VHo, VLo, VHo};
#pragma unroll
    for (int p = 0; p < 3; p++) {
        uint32_t ab = sb + AO2[p], vb = sb + BO2[p];
#pragma unroll
        for (int s = 0; s < 8; s++) {
            int half = s >> 2, kb = (s & 3) * 32;
            uint32_t a[4], b0[4];
            ldsm4(ab + half * 4096 + SWZ((jt + drA + lr) * 128 + kb + dcA), a);
            ldsm4t(vb + SWZ((16 * s + drA + lr) * 128 + cb2 + dcA), b0);
            mma16816(f[0], a, b0);
            mma16816(f[1], a, b0 + 2);
        }
    }
    int q = lane & 3, g = lane >> 2;
    int cbase = (wid >> 1) * 16;
#pragma unroll
    for (int i = 0; i < 2; i++) {
        int c = cbase + i * 8 + 2 * q;
        int j = jt + g;
        *(float2*)&g_pF[(pfbase + j) * 64 + c]     = make_float2(f[i][0], f[i][1]);
        *(float2*)&g_pF[(pfbase + j + 8) * 64 + c] = make_float2(f[i][2], f[i][3]);
    }
}

// ---------------- fused fc0 + DFT --------------------------------------------
#define F0_VH 0
#define F0_VL 16384
#define F0_BH 32768
#define F0_BL 40960
#define F0_W0 49152
#define F0_SZ 50176

__global__ __launch_bounds__(256, 3)
void fc0dft_kernel(const float* __restrict__ xg, const float* __restrict__ tg,
                   const float* __restrict__ w0, const float* __restrict__ b0) {
    extern __shared__ char smc[];
    uint32_t sb = smem_u32(smc);
    float* w0s = (float*)(smc + F0_W0);       // 128
    float* b0s = w0s + 128;                   // 64
    int tid = threadIdx.x, wid = tid >> 5, lane = tid & 31;
    int b = blockIdx.y, n0 = blockIdx.x * NT;

    if (tid < 128) w0s[tid] = w0[tid];
    if (tid < 64)  b0s[tid] = b0[tid];
    // basD tiles (half stride 4096)
    for (int i = tid; i < 512; i += 256) {
        int half = i >> 8, rest = i & 255, j = rest >> 3, q = rest & 7;
        uint32_t so = half * 4096 + SWZ(j * 128 + q * 16);
        *(uint4*)(smc + F0_BH + so) = ((const uint4*)(g_basDH + (size_t)j * NN + n0 + half * 64))[q];
        *(uint4*)(smc + F0_BL + so) = ((const uint4*)(g_basDL + (size_t)j * NN + n0 + half * 64))[q];
    }
    __syncthreads();

    // each thread: one n-row half (32 c)
    int n = tid >> 1, c0 = (tid & 1) * 32;
    float xv = xg[(size_t)b * NN + n0 + n], tv = tg[(size_t)b * NN + n0 + n];
    uint32_t hw[16], lw[16];
#pragma unroll
    for (int k = 0; k < 16; k++) {
        int c = c0 + 2 * k;
        float v0 = fmaf(w0s[c],     xv, fmaf(w0s[64 + c],     tv, b0s[c]));
        float v1 = fmaf(w0s[c + 1], xv, fmaf(w0s[64 + c + 1], tv, b0s[c + 1]));
        bf16 h0, l0, h1, l1;
        split_bf(v0, h0, l0);
        split_bf(v1, h1, l1);
        hw[k] = pack_bf(h0, h1);
        lw[k] = pack_bf(l0, l1);
    }
    size_t ro = ((size_t)b * NN + n0 + n) * 64 + c0;
#pragma unroll
    for (int g4 = 0; g4 < 4; g4++) {
        uint4 hv = make_uint4(hw[4 * g4], hw[4 * g4 + 1], hw[4 * g4 + 2], hw[4 * g4 + 3]);
        uint4 lv = make_uint4(lw[4 * g4], lw[4 * g4 + 1], lw[4 * g4 + 2], lw[4 * g4 + 3]);
        *(uint4*)(g_hH0 + ro + 8 * g4) = hv;
        *(uint4*)(g_hL0 + ro + 8 * g4) = lv;
        uint32_t so = SWZ(n * 128 + c0 * 2 + g4 * 16);
        *(uint4*)(smc + F0_VH + so) = hv;
        *(uint4*)(smc + F0_VL + so) = lv;
    }
    __syncthreads();
    dft_core8(sb, F0_VH, F0_VL, F0_BH, F0_BL, wid, lane,
              ((size_t)b * TBC + blockIdx.x) * J2);
}

// ---------------- fused reduce + modemix (1024 thr) --------------------------
__global__ __launch_bounds__(1024)
void reduce_modemix_kernel(const float* __restrict__ swr,
                           const float* __restrict__ swi) {
    __shared__ float fs[64 * 33];   // [c][j]
    int b = blockIdx.x, tid = threadIdx.x;
    for (int idx = tid; idx < 2048; idx += 1024) {
        int j = idx >> 6, c = idx & 63;
        float s = 0.0f;
        const float* p = &g_pF[((size_t)b * TBC) * (J2 * 64) + idx];
#pragma unroll 4
        for (int ch = 0; ch < TBC; ch++) s += p[(size_t)ch * (J2 * 64)];
        fs[c * 33 + j] = s;
    }
    __syncthreads();
    int m = tid & 15, o = tid >> 4;   // 16 m x 64 o
    float re = 0.0f, im = 0.0f;
    for (int i = 0; i < 64; i++) {
        float fr = fs[i * 33 + 2 * m];
        float fn = fs[i * 33 + 2 * m + 1];
        float wr = swr[(i * 64 + o) * 16 + m];
        float wi = swi[(i * 64 + o) * 16 + m];
        re = fmaf(fr, wr, fmaf(fn, wi, re));
        im = fmaf(fr, wi, fmaf(-fn, wr, im));
    }
    float cm = (m == 0 ? 1.0f : 2.0f) / (float)NN;
    bf16 z = __float2bfloat16(0.0f);
    float g0 = cm * re;
    float g1 = -cm * im;
    size_t r = ((size_t)b * 64 + o) * 64;
    bf16 h, l;
    split_bf(g0, h, l);
    g_GpB1[r + 2 * m] = h;      g_GpB1[r + 32 + 2 * m] = h;
    g_GpB2[r + 2 * m] = l;      g_GpB2[r + 32 + 2 * m] = z;
    split_bf(g1, h, l);
    g_GpB1[r + 2 * m + 1] = h;  g_GpB1[r + 32 + 2 * m + 1] = h;
    g_GpB2[r + 2 * m + 1] = l;  g_GpB2[r + 32 + 2 * m + 1] = z;
}

// ---------------- fused layer: conv + synthesis (+gelu) (+DFT) ----------------
#define MM_HH 0
#define MM_HL 16384
#define MM_BA 32768
#define MM_WH 49152
#define MM_WL 57344
#define MM_G1 65536
#define MM_G2 73728
#define MM_CB 81920
#define MM_SZ 82432

template <bool GELU, bool DFT>
__global__ __launch_bounds__(256, 2)
void mma_layer(int dir, int layer, const float* __restrict__ cb_all) {
    extern __shared__ char smc[];
    uint32_t sb = smem_u32(smc);
    int tid = threadIdx.x, wid = tid >> 5, lane = tid & 31;
    int b = blockIdx.y, n0 = blockIdx.x * NT;

    const bf16* hHsrc = (dir ? g_hH1 : g_hH0) + ((size_t)b * NN + n0) * 64;
    const bf16* hLsrc = (dir ? g_hL1 : g_hL0) + ((size_t)b * NN + n0) * 64;
    bf16* hHdst = (dir ? g_hH0 : g_hH1) + ((size_t)b * NN + n0) * 64;
    bf16* hLdst = (dir ? g_hL0 : g_hL1) + ((size_t)b * NN + n0) * 64;

    for (int i = tid; i < 1024; i += 256) {
        int r = i >> 3, q = i & 7;
        uint32_t so = SWZ(r * 128 + q * 16);
        *(uint4*)(smc + MM_HH + so) = ((const uint4*)(hHsrc + (size_t)r * 64))[q];
        *(uint4*)(smc + MM_HL + so) = ((const uint4*)(hLsrc + (size_t)r * 64))[q];
        *(uint4*)(smc + MM_BA + so) = ((const uint4*)(g_basA + (size_t)(n0 + r) * 64))[q];
    }
    for (int i = tid; i < 512; i += 256) {
        int r = i >> 3, q = i & 7;
        uint32_t so = SWZ(r * 128 + q * 16);
        *(uint4*)(smc + MM_WH + so) = ((const uint4*)(g_cwH + (size_t)(layer * 64 + r) * 64))[q];
        *(uint4*)(smc + MM_WL + so) = ((const uint4*)(g_cwL + (size_t)(layer * 64 + r) * 64))[q];
        *(uint4*)(smc + MM_G1 + so) = ((const uint4*)(g_GpB1 + ((size_t)b * 64 + r) * 64))[q];
        *(uint4*)(smc + MM_G2 + so) = ((const uint4*)(g_GpB2 + ((size_t)b * 64 + r) * 64))[q];
    }
    if (tid < 64) ((float*)(smc + MM_CB))[tid] = cb_all[layer * 64 + tid];
    __syncthreads();

    // ---- main GEMM: 8 warps, warp = 16 n-rows x 64 o-cols -------------------
    int lr = lane & 7, li = lane >> 3;
    int drA = (li & 1) * 8, dcA = (li >> 1) * 16;
    int drB = (li >> 1) * 8, dcB = (li & 1) * 16;
    int rA0 = 16 * wid;

    float acc[8][4];
#pragma unroll
    for (int nt = 0; nt < 8; nt++)
#pragma unroll
        for (int k = 0; k < 4; k++) acc[nt][k] = 0.0f;

    const int AO[5] = {MM_HH, MM_HL, MM_HH, MM_BA, MM_BA};
    const int BO[5] = {MM_WH, MM_WH, MM_WL, MM_G1, MM_G2};
#pragma unroll
    for (int p = 0; p < 5; p++) {
        uint32_t ab = sb + AO[p], bbse = sb + BO[p];
#pragma unroll
        for (int s = 0; s < 4; s++) {
            int kb = s * 32;
            uint32_t a0[4];
            ldsm4(ab + SWZ((rA0 + drA + lr) * 128 + kb + dcA), a0);
#pragma unroll
            for (int np = 0; np < 4; np++) {
                uint32_t bb[4];
                ldsm4(bbse + SWZ((np * 16 + drB + lr) * 128 + kb + dcB), bb);
                mma16816(acc[2 * np],     a0, bb);
                mma16816(acc[2 * np + 1], a0, bb + 2);
            }
        }
    }
    __syncthreads();   // all reads of operand smem done

    // ---- epilogue: bias + gelu, write vH/vL into HH/HL regions --------------
    int q = lane & 3, g = lane >> 2;
    const float* cbs = (const float*)(smc + MM_CB);
#pragma unroll
    for (int nt = 0; nt < 8; nt++) {
        int o0 = nt * 8 + 2 * q;
        int r0 = 16 * wid + g;
        float v0 = acc[nt][0] + cbs[o0];
        float v1 = acc[nt][1] + cbs[o0 + 1];
        float v2 = acc[nt][2] + cbs[o0];
        float v3 = acc[nt][3] + cbs[o0 + 1];
        if (GELU) {
            v0 = gelu_exact(v0); v1 = gelu_exact(v1);
            v2 = gelu_exact(v2); v3 = gelu_exact(v3);
        }
        bf16 h0, l0, h1, l1;
        split_bf(v0, h0, l0); split_bf(v1, h1, l1);
        *(uint32_t*)(smc + MM_HH + SWZ(r0 * 128 + o0 * 2)) = pack_bf(h0, h1);
        *(uint32_t*)(smc + MM_HL + SWZ(r0 * 128 + o0 * 2)) = pack_bf(l0, l1);
        split_bf(v2, h0, l0); split_bf(v3, h1, l1);
        *(uint32_t*)(smc + MM_HH + SWZ((r0 + 8) * 128 + o0 * 2)) = pack_bf(h0, h1);
        *(uint32_t*)(smc + MM_HL + SWZ((r0 + 8) * 128 + o0 * 2)) = pack_bf(l0, l1);
    }
    if (DFT) {
        // basD tiles into (dead) WH/WL regions, half stride 4096
        for (int i = tid; i < 512; i += 256) {
            int half = i >> 8, rest = i & 255, j = rest >> 3, qq = rest & 7;
            uint32_t so = half * 4096 + SWZ(j * 128 + qq * 16);
            *(uint4*)(smc + MM_WH + so) = ((const uint4*)(g_basDH + (size_t)j * NN + n0 + half * 64))[qq];
            *(uint4*)(smc + MM_WL + so) = ((const uint4*)(g_basDL + (size_t)j * NN + n0 + half * 64))[qq];
        }
    }
    __syncthreads();

    // ---- coalesced copy-out of vH/vL to gmem --------------------------------
    for (int i = tid; i < 1024; i += 256) {
        int r = i >> 3, qq = i & 7;
        uint32_t so = SWZ(r * 128 + qq * 16);
        ((uint4*)(hHdst + (size_t)r * 64))[qq] = *(uint4*)(smc + MM_HH + so);
        ((uint4*)(hLdst + (size_t)r * 64))[qq] = *(uint4*)(smc + MM_HL + so);
    }
    if (DFT) {
        dft_core8(sb, MM_HH, MM_HL, MM_WH, MM_WL, wid, lane,
                  ((size_t)b * TBC + blockIdx.x) * J2);
    }
}

// ---------------- fc1 + gelu + fc2 via MMA -----------------------------------
#define FC_HH 0
#define FC_HL 16384
#define FC_WH 32768
#define FC_WL 49152
#define FC_B1 65536
#define FC_W2 66048
#define FC_SZ 66560

__global__ __launch_bounds__(256, 2)
void fc12_kernel(const float* __restrict__ b1, const float* __restrict__ w2,
                 const float* __restrict__ b2, float* __restrict__ out) {
    extern __shared__ char smc[];
    uint32_t sb = smem_u32(smc);
    int tid = threadIdx.x, wid = tid >> 5, lane = tid & 31;
    int b = blockIdx.y, n0 = blockIdx.x * NT;

    const bf16* hH = g_hH0 + ((size_t)b * NN + n0) * 64;
    const bf16* hL = g_hL0 + ((size_t)b * NN + n0) * 64;
    for (int i = tid; i < 1024; i += 256) {
        int r = i >> 3, q = i & 7;
        uint32_t so = SWZ(r * 128 + q * 16);
        *(uint4*)(smc + FC_HH + so) = ((const uint4*)(hH + (size_t)r * 64))[q];
        *(uint4*)(smc + FC_HL + so) = ((const uint4*)(hL + (size_t)r * 64))[q];
        *(uint4*)(smc + FC_WH + so) = ((const uint4*)(g_w1TH + (size_t)r * 64))[q];
        *(uint4*)(smc + FC_WL + so) = ((const uint4*)(g_w1TL + (size_t)r * 64))[q];
    }
    if (tid < 128) {
        ((float*)(smc + FC_B1))[tid] = b1[tid];
        ((float*)(smc + FC_W2))[tid] = w2[tid];
    }
    __syncthreads();

    int lr = lane & 7, li = lane >> 3;
    int drA = (li & 1) * 8, dcA = (li >> 1) * 16;
    int drB = (li >> 1) * 8, dcB = (li & 1) * 16;
    int rA0 = 16 * wid;

    float acc[16][4];
#pragma unroll
    for (int nt = 0; nt < 16; nt++)
#pragma unroll
        for (int k = 0; k < 4; k++) acc[nt][k] = 0.0f;

    const int AO[3] = {FC_HH, FC_HL, FC_HH};
    const int BO[3] = {FC_WH, FC_WH, FC_WL};
#pragma unroll
    for (int p = 0; p < 3; p++) {
        uint32_t ab = sb + AO[p], bbse = sb + BO[p];
#pragma unroll
        for (int s = 0; s < 4; s++) {
            int kb = s * 32;
            uint32_t a[4];
            ldsm4(ab + SWZ((rA0 + drA + lr) * 128 + kb + dcA), a);
#pragma unroll
            for (int np = 0; np < 8; np++) {
                uint32_t bb[4];
                ldsm4(bbse + SWZ((np * 16 + drB + lr) * 128 + kb + dcB), bb);
                mma16816(acc[2 * np],     a, bb);
                mma16816(acc[2 * np + 1], a, bb + 2);
            }
        }
    }

    // epilogue: gelu(acc + b1) . w2, reduce over j
    int q = lane & 3, g = lane >> 2;
    const float* b1s = (const float*)(smc + FC_B1);
    const float* w2s = (const float*)(smc + FC_W2);
    float s0 = 0.0f, s1 = 0.0f;
#pragma unroll
    for (int nt = 0; nt < 16; nt++) {
        int j0 = nt * 8 + 2 * q;
        s0 = fmaf(w2s[j0],     gelu_exact(acc[nt][0] + b1s[j0]),     s0);
        s0 = fmaf(w2s[j0 + 1], gelu_exact(acc[nt][1] + b1s[j0 + 1]), s0);
        s1 = fmaf(w2s[j0],     gelu_exact(acc[nt][2] + b1s[j0]),     s1);
        s1 = fmaf(w2s[j0 + 1], gelu_exact(acc[nt][3] + b1s[j0 + 1]), s1);
    }
    s0 += __shfl_xor_sync(0xffffffffu, s0, 1);
    s0 += __shfl_xor_sync(0xffffffffu, s0, 2);
    s1 += __shfl_xor_sync(0xffffffffu, s1, 1);
    s1 += __shfl_xor_sync(0xffffffffu, s1, 2);
    if (q == 0) {
        float bv = b2[0];
        out[(size_t)b * NN + n0 + 16 * wid + g]     = s0 + bv;
        out[(size_t)b * NN + n0 + 16 * wid + g + 8] = s1 + bv;
    }
}

// ---------------- host launcher ----------------------------------------------
extern "C" void kernel_launch(void* const* d_in, const int* in_sizes, int n_in,
                              void* d_out, int out_size) {
    const float* x    = (const float*)d_in[0];
    const float* t    = (const float*)d_in[1];
    const float* fc0w = (const float*)d_in[2];
    const float* fc0b = (const float*)d_in[3];
    const float* swr  = (const float*)d_in[4];
    const float* swi  = (const float*)d_in[5];
    const float* cw   = (const float*)d_in[6];
    const float* cb   = (const float*)d_in[7];
    const float* w1   = (const float*)d_in[8];
    const float* b1   = (const float*)d_in[9];
    const float* w2   = (const float*)d_in[10];
    const float* b2   = (const float*)d_in[11];
    float* out = (float*)d_out;

    cudaFuncSetAttribute(mma_layer<true,  true >, cudaFuncAttributeMaxDynamicSharedMemorySize, MM_SZ);
    cudaFuncSetAttribute(mma_layer<false, false>, cudaFuncAttributeMaxDynamicSharedMemorySize, MM_SZ);
    cudaFuncSetAttribute(fc0dft_kernel, cudaFuncAttributeMaxDynamicSharedMemorySize, F0_SZ);
    cudaFuncSetAttribute(fc12_kernel, cudaFuncAttributeMaxDynamicSharedMemorySize, FC_SZ);

    dim3 g(TBC, BB);
    prep_basis<<<NN / 256, 256>>>();
    prep_w<<<(4 * 4096 + 128 * 64 + 255) / 256, 256>>>(cw, w1);

    fc0dft_kernel<<<g, 256, F0_SZ>>>(x, t, fc0w, fc0b);

    const size_t SWL = (size_t)64 * 64 * 16;
    reduce_modemix_kernel<<<BB, 1024>>>(swr + 0 * SWL, swi + 0 * SWL);
    mma_layer<true, true><<<g, 256, MM_SZ>>>(0, 0, cb);

    reduce_modemix_kernel<<<BB, 1024>>>(swr + 1 * SWL, swi + 1 * SWL);
    mma_layer<true, true><<<g, 256, MM_SZ>>>(1, 1, cb);

    reduce_modemix_kernel<<<BB, 1024>>>(swr + 2 * SWL, swi + 2 * SWL);
    mma_layer<true, true><<<g, 256, MM_SZ>>>(0, 2, cb);

    reduce_modemix_kernel<<<BB, 1024>>>(swr + 3 * SWL, swi + 3 * SWL);
    mma_layer<false, false><<<g, 256, MM_SZ>>>(1, 3, cb);

    fc12_kernel<<<g, 256, FC_SZ>>>(b1, w2, b2, out);
}

// round 9
// speedup vs baseline: 3.5979x; 1.2542x over previous
#include <cuda_runtime.h>
#include <cuda_bf16.h>
#include <math.h>
#include <stdint.h>
#include <stddef.h>

#define BB 64
#define NN 8192
#define MODES 16
#define J2 32
#define NT 128
#define TBC (NN / NT)

typedef __nv_bfloat16 bf16;

// ---------------- device scratch --------------------------------------------
__device__ bf16  g_hH0[(size_t)BB * NN * 64];
__device__ bf16  g_hL0[(size_t)BB * NN * 64];
__device__ bf16  g_hH1[(size_t)BB * NN * 64];
__device__ bf16  g_hL1[(size_t)BB * NN * 64];
__device__ float g_pF[(size_t)BB * TBC * J2 * 64];    // [b][chunk][j][c]
__device__ bf16  g_basDH[(size_t)J2 * NN];            // [j][n] hi
__device__ bf16  g_basDL[(size_t)J2 * NN];            // [j][n] lo
__device__ bf16  g_cwH[4 * 64 * 64];                  // [l][o][c]
__device__ bf16  g_cwL[4 * 64 * 64];
__device__ bf16  g_GpP[(size_t)BB * 64 * 64];         // [b][o][ gh(32) | gl(32) ]
__device__ bf16  g_w1TH[128 * 64];                    // [j][c]
__device__ bf16  g_w1TL[128 * 64];

// ---------------- helpers ----------------------------------------------------
#define SWZ(x) ((x) ^ (((x) >> 3) & 0x70))

__device__ __forceinline__ uint32_t smem_u32(const void* p) {
    uint32_t a;
    asm("{ .reg .u64 t; cvta.to.shared.u64 t, %1; cvt.u32.u64 %0, t; }" : "=r"(a) : "l"(p));
    return a;
}
__device__ __forceinline__ void ldsm4(uint32_t a, uint32_t* r) {
    asm volatile("ldmatrix.sync.aligned.m8n8.x4.shared.b16 {%0,%1,%2,%3}, [%4];"
                 : "=r"(r[0]), "=r"(r[1]), "=r"(r[2]), "=r"(r[3]) : "r"(a));
}
__device__ __forceinline__ void ldsm4t(uint32_t a, uint32_t* r) {
    asm volatile("ldmatrix.sync.aligned.m8n8.x4.trans.shared.b16 {%0,%1,%2,%3}, [%4];"
                 : "=r"(r[0]), "=r"(r[1]), "=r"(r[2]), "=r"(r[3]) : "r"(a));
}
__device__ __forceinline__ void mma16816(float* d, const uint32_t* a, const uint32_t* b) {
    asm volatile(
        "mma.sync.aligned.m16n8k16.row.col.f32.bf16.bf16.f32 "
        "{%0,%1,%2,%3},{%4,%5,%6,%7},{%8,%9},{%0,%1,%2,%3};"
        : "+f"(d[0]), "+f"(d[1]), "+f"(d[2]), "+f"(d[3])
        : "r"(a[0]), "r"(a[1]), "r"(a[2]), "r"(a[3]), "r"(b[0]), "r"(b[1]));
}
__device__ __forceinline__ float gelu_exact(float v) {
    return 0.5f * v * (1.0f + erff(v * 0.70710678118654752f));
}
__device__ __forceinline__ void split_bf(float v, bf16& h, bf16& l) {
    h = __float2bfloat16(v);
    l = __float2bfloat16(v - __bfloat162float(h));
}
__device__ __forceinline__ uint32_t pack_bf(bf16 a, bf16 b) {
    return (uint32_t)__bfloat16_as_ushort(a) | ((uint32_t)__bfloat16_as_ushort(b) << 16);
}

// ---------------- prep -------------------------------------------------------
__global__ void prep_basis() {
    int n = blockIdx.x * 256 + threadIdx.x;
    if (n >= NN) return;
#pragma unroll
    for (int m = 0; m < MODES; m++) {
        int r = (m * n) & (NN - 1);
        float tf = 2.0f * (float)r / (float)NN;
        float s, c;
        sincospif(tf, &s, &c);
        bf16 h, l;
        split_bf(c, h, l);
        g_basDH[(size_t)(2 * m) * NN + n] = h;
        g_basDL[(size_t)(2 * m) * NN + n] = l;
        split_bf(s, h, l);
        g_basDH[(size_t)(2 * m + 1) * NN + n] = h;
        g_basDL[(size_t)(2 * m + 1) * NN + n] = l;
    }
}

__global__ void prep_w(const float* __restrict__ cw, const float* __restrict__ w1) {
    int idx = blockIdx.x * 256 + threadIdx.x;
    if (idx < 4 * 64 * 64) {
        bf16 h, l;
        split_bf(cw[idx], h, l);
        g_cwH[idx] = h; g_cwL[idx] = l;
    } else if (idx < 4 * 64 * 64 + 128 * 64) {
        int i2 = idx - 4 * 64 * 64;
        int c = i2 >> 7, j = i2 & 127;
        bf16 h, l;
        split_bf(w1[c * 128 + j], h, l);
        g_w1TH[j * 64 + c] = h; g_w1TL[j * 64 + c] = l;
    }
}

// ---------------- DFT MMA core (8 warps) -------------------------------------
// F[32j x 64c] = (basDH+basDL)[j][n] x (vH+vL)[n][c]  (3 split terms)
// vH/vL: [n(128)][c(64)] swizzled; basD: [half(2)][j(32)][n'(64)] swizzled,
// half stride = 4096 B.  8 warps: jt=(w&1)*16, cbase=(w>>1)*16.
__device__ __forceinline__ void dft_core8(uint32_t sb, int VHo, int VLo, int BHo, int BLo,
                                          int wid, int lane, size_t pfbase) {
    int lr = lane & 7, li = lane >> 3;
    int drA = (li & 1) * 8, dcA = (li >> 1) * 16;
    int jt = (wid & 1) * 16;
    int cb2 = (wid >> 1) * 32;   // byte col base
    float f[2][4];
#pragma unroll
    for (int i = 0; i < 2; i++)
#pragma unroll
        for (int k = 0; k < 4; k++) f[i][k] = 0.0f;

#pragma unroll
    for (int s = 0; s < 8; s++) {
        int half = s >> 2, kb = (s & 3) * 32;
        uint32_t ah[4], al[4], bh[4], bl[4];
        ldsm4(sb + BHo + half * 4096 + SWZ((jt + drA + lr) * 128 + kb + dcA), ah);
        ldsm4(sb + BLo + half * 4096 + SWZ((jt + drA + lr) * 128 + kb + dcA), al);
        ldsm4t(sb + VHo + SWZ((16 * s + drA + lr) * 128 + cb2 + dcA), bh);
        ldsm4t(sb + VLo + SWZ((16 * s + drA + lr) * 128 + cb2 + dcA), bl);
        mma16816(f[0], ah, bh); mma16816(f[1], ah, bh + 2);
        mma16816(f[0], al, bh); mma16816(f[1], al, bh + 2);
        mma16816(f[0], ah, bl); mma16816(f[1], ah, bl + 2);
    }
    int q = lane & 3, g = lane >> 2;
    int cbase = (wid >> 1) * 16;
#pragma unroll
    for (int i = 0; i < 2; i++) {
        int c = cbase + i * 8 + 2 * q;
        int j = jt + g;
        *(float2*)&g_pF[(pfbase + j) * 64 + c]     = make_float2(f[i][0], f[i][1]);
        *(float2*)&g_pF[(pfbase + j + 8) * 64 + c] = make_float2(f[i][2], f[i][3]);
    }
}

// ---------------- fused fc0 + DFT --------------------------------------------
#define F0_VH 0
#define F0_VL 16384
#define F0_BH 32768
#define F0_BL 40960
#define F0_W0 49152
#define F0_SZ 50176

__global__ __launch_bounds__(256, 3)
void fc0dft_kernel(const float* __restrict__ xg, const float* __restrict__ tg,
                   const float* __restrict__ w0, const float* __restrict__ b0) {
    extern __shared__ char smc[];
    uint32_t sb = smem_u32(smc);
    float* w0s = (float*)(smc + F0_W0);       // 128
    float* b0s = w0s + 128;                   // 64
    int tid = threadIdx.x, wid = tid >> 5, lane = tid & 31;
    int b = blockIdx.y, n0 = blockIdx.x * NT;

    if (tid < 128) w0s[tid] = w0[tid];
    if (tid < 64)  b0s[tid] = b0[tid];
    for (int i = tid; i < 512; i += 256) {
        int half = i >> 8, rest = i & 255, j = rest >> 3, q = rest & 7;
        uint32_t so = half * 4096 + SWZ(j * 128 + q * 16);
        *(uint4*)(smc + F0_BH + so) = ((const uint4*)(g_basDH + (size_t)j * NN + n0 + half * 64))[q];
        *(uint4*)(smc + F0_BL + so) = ((const uint4*)(g_basDL + (size_t)j * NN + n0 + half * 64))[q];
    }
    __syncthreads();

    int n = tid >> 1, c0 = (tid & 1) * 32;
    float xv = xg[(size_t)b * NN + n0 + n], tv = tg[(size_t)b * NN + n0 + n];
    uint32_t hw[16], lw[16];
#pragma unroll
    for (int k = 0; k < 16; k++) {
        int c = c0 + 2 * k;
        float v0 = fmaf(w0s[c],     xv, fmaf(w0s[64 + c],     tv, b0s[c]));
        float v1 = fmaf(w0s[c + 1], xv, fmaf(w0s[64 + c + 1], tv, b0s[c + 1]));
        bf16 h0, l0, h1, l1;
        split_bf(v0, h0, l0);
        split_bf(v1, h1, l1);
        hw[k] = pack_bf(h0, h1);
        lw[k] = pack_bf(l0, l1);
    }
    size_t ro = ((size_t)b * NN + n0 + n) * 64 + c0;
#pragma unroll
    for (int g4 = 0; g4 < 4; g4++) {
        uint4 hv = make_uint4(hw[4 * g4], hw[4 * g4 + 1], hw[4 * g4 + 2], hw[4 * g4 + 3]);
        uint4 lv = make_uint4(lw[4 * g4], lw[4 * g4 + 1], lw[4 * g4 + 2], lw[4 * g4 + 3]);
        *(uint4*)(g_hH0 + ro + 8 * g4) = hv;
        *(uint4*)(g_hL0 + ro + 8 * g4) = lv;
        uint32_t so = SWZ(n * 128 + c0 * 2 + g4 * 16);
        *(uint4*)(smc + F0_VH + so) = hv;
        *(uint4*)(smc + F0_VL + so) = lv;
    }
    __syncthreads();
    dft_core8(sb, F0_VH, F0_VL, F0_BH, F0_BL, wid, lane,
              ((size_t)b * TBC + blockIdx.x) * J2);
}

// ---------------- fused reduce + modemix (1024 thr) --------------------------
__global__ __launch_bounds__(1024)
void reduce_modemix_kernel(const float* __restrict__ swr,
                           const float* __restrict__ swi) {
    __shared__ float fs[64 * 33];   // [c][j]
    int b = blockIdx.x, tid = threadIdx.x;
    for (int idx = tid; idx < 2048; idx += 1024) {
        int j = idx >> 6, c = idx & 63;
        float s = 0.0f;
        const float* p = &g_pF[((size_t)b * TBC) * (J2 * 64) + idx];
#pragma unroll 4
        for (int ch = 0; ch < TBC; ch++) s += p[(size_t)ch * (J2 * 64)];
        fs[c * 33 + j] = s;
    }
    __syncthreads();
    int m = tid & 15, o = tid >> 4;   // 16 m x 64 o
    float re = 0.0f, im = 0.0f;
    for (int i = 0; i < 64; i++) {
        float fr = fs[i * 33 + 2 * m];
        float fn = fs[i * 33 + 2 * m + 1];
        float wr = swr[(i * 64 + o) * 16 + m];
        float wi = swi[(i * 64 + o) * 16 + m];
        re = fmaf(fr, wr, fmaf(fn, wi, re));
        im = fmaf(fr, wi, fmaf(-fn, wr, im));
    }
    float cm = (m == 0 ? 1.0f : 2.0f) / (float)NN;
    float g0 = cm * re;
    float g1 = -cm * im;
    size_t r = ((size_t)b * 64 + o) * 64;
    bf16 h, l;
    split_bf(g0, h, l);
    g_GpP[r + 2 * m] = h;      g_GpP[r + 32 + 2 * m] = l;
    split_bf(g1, h, l);
    g_GpP[r + 2 * m + 1] = h;  g_GpP[r + 32 + 2 * m + 1] = l;
}

// ---------------- fused layer: conv + synthesis (+gelu) (+DFT) ----------------
// smem: HH 16K | HL 16K | WH 8K | WL 8K | BDH 8K | BDL 8K | G 8K | CB
#define MM_HH  0
#define MM_HL  16384
#define MM_WH  32768
#define MM_WL  40960
#define MM_BDH 49152
#define MM_BDL 57344
#define MM_G   65536
#define MM_CB  73728
#define MM_SZ  73984

template <bool GELU, bool DFT>
__global__ __launch_bounds__(256, 3)
void mma_layer(int dir, int layer, const float* __restrict__ cb_all) {
    extern __shared__ char smc[];
    uint32_t sb = smem_u32(smc);
    int tid = threadIdx.x, wid = tid >> 5, lane = tid & 31;
    int b = blockIdx.y, n0 = blockIdx.x * NT;

    const bf16* hHsrc = (dir ? g_hH1 : g_hH0) + ((size_t)b * NN + n0) * 64;
    const bf16* hLsrc = (dir ? g_hL1 : g_hL0) + ((size_t)b * NN + n0) * 64;
    bf16* hHdst = (dir ? g_hH0 : g_hH1) + ((size_t)b * NN + n0) * 64;
    bf16* hLdst = (dir ? g_hL0 : g_hL1) + ((size_t)b * NN + n0) * 64;

    for (int i = tid; i < 1024; i += 256) {
        int r = i >> 3, q = i & 7;
        uint32_t so = SWZ(r * 128 + q * 16);
        *(uint4*)(smc + MM_HH + so) = ((const uint4*)(hHsrc + (size_t)r * 64))[q];
        *(uint4*)(smc + MM_HL + so) = ((const uint4*)(hLsrc + (size_t)r * 64))[q];
    }
    for (int i = tid; i < 512; i += 256) {
        int r = i >> 3, q = i & 7;
        uint32_t so = SWZ(r * 128 + q * 16);
        *(uint4*)(smc + MM_WH + so) = ((const uint4*)(g_cwH + (size_t)(layer * 64 + r) * 64))[q];
        *(uint4*)(smc + MM_WL + so) = ((const uint4*)(g_cwL + (size_t)(layer * 64 + r) * 64))[q];
        *(uint4*)(smc + MM_G  + so) = ((const uint4*)(g_GpP + ((size_t)b * 64 + r) * 64))[q];
        // basD tiles: [half][j(32)][128B], half stride 4096
        int half = i >> 8, rest = i & 255, j = rest >> 3, qq = rest & 7;
        uint32_t so2 = half * 4096 + SWZ(j * 128 + qq * 16);
        *(uint4*)(smc + MM_BDH + so2) = ((const uint4*)(g_basDH + (size_t)j * NN + n0 + half * 64))[qq];
        *(uint4*)(smc + MM_BDL + so2) = ((const uint4*)(g_basDL + (size_t)j * NN + n0 + half * 64))[qq];
    }
    if (tid < 64) ((float*)(smc + MM_CB))[tid] = cb_all[layer * 64 + tid];
    __syncthreads();

    // ---- GEMM: 8 warps, warp = 16 n-rows x 64 o-cols ------------------------
    int lr = lane & 7, li = lane >> 3;
    int drA = (li & 1) * 8, dcA = (li >> 1) * 16;
    int drB = (li >> 1) * 8, dcB = (li & 1) * 16;
    int rA0 = 16 * wid;

    float acc[8][4];
#pragma unroll
    for (int nt = 0; nt < 8; nt++)
#pragma unroll
        for (int k = 0; k < 4; k++) acc[nt][k] = 0.0f;

    // conv: (Hh+Hl)(Wh+Wl) 3-term, fragments reused
#pragma unroll
    for (int s = 0; s < 4; s++) {
        int kb = s * 32;
        uint32_t ah[4], al[4];
        ldsm4(sb + MM_HH + SWZ((rA0 + drA + lr) * 128 + kb + dcA), ah);
        ldsm4(sb + MM_HL + SWZ((rA0 + drA + lr) * 128 + kb + dcA), al);
#pragma unroll
        for (int np = 0; np < 4; np++) {
            uint32_t bb[4];
            ldsm4(sb + MM_WH + SWZ((np * 16 + drB + lr) * 128 + kb + dcB), bb);
            mma16816(acc[2 * np],     ah, bb);
            mma16816(acc[2 * np + 1], ah, bb + 2);
            mma16816(acc[2 * np],     al, bb);
            mma16816(acc[2 * np + 1], al, bb + 2);
            ldsm4(sb + MM_WL + SWZ((np * 16 + drB + lr) * 128 + kb + dcB), bb);
            mma16816(acc[2 * np],     ah, bb);
            mma16816(acc[2 * np + 1], ah, bb + 2);
        }
    }
    // synthesis: A = trans(basD half tile), B = packed G (gh bytes 0-63, gl 64-127)
    {
        int halfS = rA0 >> 6;
        int colA = (rA0 & 63) * 2 + (li & 1) * 16;
        int rowA = (li >> 1) * 8 + lr;
#pragma unroll
        for (int s = 0; s < 2; s++) {
            int kb = s * 32;
            uint32_t ah[4], al[4];
            ldsm4t(sb + MM_BDH + halfS * 4096 + SWZ((s * 16 + rowA) * 128 + colA), ah);
            ldsm4t(sb + MM_BDL + halfS * 4096 + SWZ((s * 16 + rowA) * 128 + colA), al);
#pragma unroll
            for (int np = 0; np < 4; np++) {
                uint32_t bb[4];
                ldsm4(sb + MM_G + SWZ((np * 16 + drB + lr) * 128 + kb + dcB), bb);
                mma16816(acc[2 * np],     ah, bb);
                mma16816(acc[2 * np + 1], ah, bb + 2);
                mma16816(acc[2 * np],     al, bb);
                mma16816(acc[2 * np + 1], al, bb + 2);
                ldsm4(sb + MM_G + SWZ((np * 16 + drB + lr) * 128 + 64 + kb + dcB), bb);
                mma16816(acc[2 * np],     ah, bb);
                mma16816(acc[2 * np + 1], ah, bb + 2);
            }
        }
    }
    __syncthreads();   // all reads of HH/HL done; epilogue overwrites them

    // ---- epilogue: bias + gelu, write vH/vL into HH/HL ----------------------
    int q = lane & 3, g = lane >> 2;
    const float* cbs = (const float*)(smc + MM_CB);
#pragma unroll
    for (int nt = 0; nt < 8; nt++) {
        int o0 = nt * 8 + 2 * q;
        int r0 = 16 * wid + g;
        float v0 = acc[nt][0] + cbs[o0];
        float v1 = acc[nt][1] + cbs[o0 + 1];
        float v2 = acc[nt][2] + cbs[o0];
        float v3 = acc[nt][3] + cbs[o0 + 1];
        if (GELU) {
            v0 = gelu_exact(v0); v1 = gelu_exact(v1);
            v2 = gelu_exact(v2); v3 = gelu_exact(v3);
        }
        bf16 h0, l0, h1, l1;
        split_bf(v0, h0, l0); split_bf(v1, h1, l1);
        *(uint32_t*)(smc + MM_HH + SWZ(r0 * 128 + o0 * 2)) = pack_bf(h0, h1);
        *(uint32_t*)(smc + MM_HL + SWZ(r0 * 128 + o0 * 2)) = pack_bf(l0, l1);
        split_bf(v2, h0, l0); split_bf(v3, h1, l1);
        *(uint32_t*)(smc + MM_HH + SWZ((r0 + 8) * 128 + o0 * 2)) = pack_bf(h0, h1);
        *(uint32_t*)(smc + MM_HL + SWZ((r0 + 8) * 128 + o0 * 2)) = pack_bf(l0, l1);
    }
    __syncthreads();

    // ---- coalesced copy-out of vH/vL to gmem --------------------------------
    for (int i = tid; i < 1024; i += 256) {
        int r = i >> 3, qq = i & 7;
        uint32_t so = SWZ(r * 128 + qq * 16);
        ((uint4*)(hHdst + (size_t)r * 64))[qq] = *(uint4*)(smc + MM_HH + so);
        ((uint4*)(hLdst + (size_t)r * 64))[qq] = *(uint4*)(smc + MM_HL + so);
    }
    if (DFT) {
        dft_core8(sb, MM_HH, MM_HL, MM_BDH, MM_BDL, wid, lane,
                  ((size_t)b * TBC + blockIdx.x) * J2);
    }
}

// ---------------- fc1 + gelu + fc2 via MMA -----------------------------------
#define FC_HH 0
#define FC_HL 16384
#define FC_WH 32768
#define FC_WL 49152
#define FC_B1 65536
#define FC_W2 66048
#define FC_SZ 66560

__global__ __launch_bounds__(256, 2)
void fc12_kernel(const float* __restrict__ b1, const float* __restrict__ w2,
                 const float* __restrict__ b2, float* __restrict__ out) {
    extern __shared__ char smc[];
    uint32_t sb = smem_u32(smc);
    int tid = threadIdx.x, wid = tid >> 5, lane = tid & 31;
    int b = blockIdx.y, n0 = blockIdx.x * NT;

    const bf16* hH = g_hH0 + ((size_t)b * NN + n0) * 64;
    const bf16* hL = g_hL0 + ((size_t)b * NN + n0) * 64;
    for (int i = tid; i < 1024; i += 256) {
        int r = i >> 3, q = i & 7;
        uint32_t so = SWZ(r * 128 + q * 16);
        *(uint4*)(smc + FC_HH + so) = ((const uint4*)(hH + (size_t)r * 64))[q];
        *(uint4*)(smc + FC_HL + so) = ((const uint4*)(hL + (size_t)r * 64))[q];
        *(uint4*)(smc + FC_WH + so) = ((const uint4*)(g_w1TH + (size_t)r * 64))[q];
        *(uint4*)(smc + FC_WL + so) = ((const uint4*)(g_w1TL + (size_t)r * 64))[q];
    }
    if (tid < 128) {
        ((float*)(smc + FC_B1))[tid] = b1[tid];
        ((float*)(smc + FC_W2))[tid] = w2[tid];
    }
    __syncthreads();

    int lr = lane & 7, li = lane >> 3;
    int drA = (li & 1) * 8, dcA = (li >> 1) * 16;
    int drB = (li >> 1) * 8, dcB = (li & 1) * 16;
    int rA0 = 16 * wid;

    float acc[16][4];
#pragma unroll
    for (int nt = 0; nt < 16; nt++)
#pragma unroll
        for (int k = 0; k < 4; k++) acc[nt][k] = 0.0f;

#pragma unroll
    for (int s = 0; s < 4; s++) {
        int kb = s * 32;
        uint32_t ah[4], al[4];
        ldsm4(sb + FC_HH + SWZ((rA0 + drA + lr) * 128 + kb + dcA), ah);
        ldsm4(sb + FC_HL + SWZ((rA0 + drA + lr) * 128 + kb + dcA), al);
#pragma unroll
        for (int np = 0; np < 8; np++) {
            uint32_t bb[4];
            ldsm4(sb + FC_WH + SWZ((np * 16 + drB + lr) * 128 + kb + dcB), bb);
            mma16816(acc[2 * np],     ah, bb);
            mma16816(acc[2 * np + 1], ah, bb + 2);
            mma16816(acc[2 * np],     al, bb);
            mma16816(acc[2 * np + 1], al, bb + 2);
            ldsm4(sb + FC_WL + SWZ((np * 16 + drB + lr) * 128 + kb + dcB), bb);
            mma16816(acc[2 * np],     ah, bb);
            mma16816(acc[2 * np + 1], ah, bb + 2);
        }
    }

    // epilogue: gelu(acc + b1) . w2, reduce over j
    int q = lane & 3, g = lane >> 2;
    const float* b1s = (const float*)(smc + FC_B1);
    const float* w2s = (const float*)(smc + FC_W2);
    float s0 = 0.0f, s1 = 0.0f;
#pragma unroll
    for (int nt = 0; nt < 16; nt++) {
        int j0 = nt * 8 + 2 * q;
        s0 = fmaf(w2s[j0],     gelu_exact(acc[nt][0] + b1s[j0]),     s0);
        s0 = fmaf(w2s[j0 + 1], gelu_exact(acc[nt][1] + b1s[j0 + 1]), s0);
        s1 = fmaf(w2s[j0],     gelu_exact(acc[nt][2] + b1s[j0]),     s1);
        s1 = fmaf(w2s[j0 + 1], gelu_exact(acc[nt][3] + b1s[j0 + 1]), s1);
    }
    s0 += __shfl_xor_sync(0xffffffffu, s0, 1);
    s0 += __shfl_xor_sync(0xffffffffu, s0, 2);
    s1 += __shfl_xor_sync(0xffffffffu, s1, 1);
    s1 += __shfl_xor_sync(0xffffffffu, s1, 2);
    if (q == 0) {
        float bv = b2[0];
        out[(size_t)b * NN + n0 + 16 * wid + g]     = s0 + bv;
        out[(size_t)b * NN + n0 + 16 * wid + g + 8] = s1 + bv;
    }
}

// ---------------- host launcher ----------------------------------------------
extern "C" void kernel_launch(void* const* d_in, const int* in_sizes, int n_in,
                              void* d_out, int out_size) {
    const float* x    = (const float*)d_in[0];
    const float* t    = (const float*)d_in[1];
    const float* fc0w = (const float*)d_in[2];
    const float* fc0b = (const float*)d_in[3];
    const float* swr  = (const float*)d_in[4];
    const float* swi  = (const float*)d_in[5];
    const float* cw   = (const float*)d_in[6];
    const float* cb   = (const float*)d_in[7];
    const float* w1   = (const float*)d_in[8];
    const float* b1   = (const float*)d_in[9];
    const float* w2   = (const float*)d_in[10];
    const float* b2   = (const float*)d_in[11];
    float* out = (float*)d_out;

    cudaFuncSetAttribute(mma_layer<true,  true >, cudaFuncAttributeMaxDynamicSharedMemorySize, MM_SZ);
    cudaFuncSetAttribute(mma_layer<false, false>, cudaFuncAttributeMaxDynamicSharedMemorySize, MM_SZ);
    cudaFuncSetAttribute(fc0dft_kernel, cudaFuncAttributeMaxDynamicSharedMemorySize, F0_SZ);
    cudaFuncSetAttribute(fc12_kernel, cudaFuncAttributeMaxDynamicSharedMemorySize, FC_SZ);

    dim3 g(TBC, BB);
    prep_basis<<<NN / 256, 256>>>();
    prep_w<<<(4 * 4096 + 128 * 64 + 255) / 256, 256>>>(cw, w1);

    fc0dft_kernel<<<g, 256, F0_SZ>>>(x, t, fc0w, fc0b);

    const size_t SWL = (size_t)64 * 64 * 16;
    reduce_modemix_kernel<<<BB, 1024>>>(swr + 0 * SWL, swi + 0 * SWL);
    mma_layer<true, true><<<g, 256, MM_SZ>>>(0, 0, cb);

    reduce_modemix_kernel<<<BB, 1024>>>(swr + 1 * SWL, swi + 1 * SWL);
    mma_layer<true, true><<<g, 256, MM_SZ>>>(1, 1, cb);

    reduce_modemix_kernel<<<BB, 1024>>>(swr + 2 * SWL, swi + 2 * SWL);
    mma_layer<true, true><<<g, 256, MM_SZ>>>(0, 2, cb);

    reduce_modemix_kernel<<<BB, 1024>>>(swr + 3 * SWL, swi + 3 * SWL);
    mma_layer<false, false><<<g, 256, MM_SZ>>>(1, 3, cb);

    fc12_kernel<<<g, 256, FC_SZ>>>(b1, w2, b2, out);
}

// round 10
// speedup vs baseline: 3.8268x; 1.0636x over previous
#include <cuda_runtime.h>
#include <cuda_bf16.h>
#include <math.h>
#include <stdint.h>
#include <stddef.h>

#define BB 64
#define NN 8192
#define MODES 16
#define J2 32
#define NT 128
#define TBC (NN / NT)

typedef __nv_bfloat16 bf16;

// ---------------- device scratch --------------------------------------------
__device__ bf16  g_hH0[(size_t)BB * NN * 64];
__device__ bf16  g_hL0[(size_t)BB * NN * 64];
__device__ bf16  g_hH1[(size_t)BB * NN * 64];
__device__ bf16  g_hL1[(size_t)BB * NN * 64];
__device__ float g_pF[(size_t)BB * TBC * J2 * 64];    // [b][chunk][j][c]
__device__ float g_F[(size_t)BB * J2 * 64];           // [b][j][c]
__device__ bf16  g_basDH[(size_t)J2 * NN];            // [j][n] hi
__device__ bf16  g_basDL[(size_t)J2 * NN];            // [j][n] lo
__device__ bf16  g_cwH[4 * 64 * 64];                  // [l][o][c]
__device__ bf16  g_cwL[4 * 64 * 64];
__device__ bf16  g_GpP[(size_t)BB * 64 * 64];         // [b][o][ gh(32) | gl(32) ]
__device__ bf16  g_w1TH[128 * 64];                    // [j][c]
__device__ bf16  g_w1TL[128 * 64];

// ---------------- helpers ----------------------------------------------------
#define SWZ(x) ((x) ^ (((x) >> 3) & 0x70))

__device__ __forceinline__ uint32_t smem_u32(const void* p) {
    uint32_t a;
    asm("{ .reg .u64 t; cvta.to.shared.u64 t, %1; cvt.u32.u64 %0, t; }" : "=r"(a) : "l"(p));
    return a;
}
__device__ __forceinline__ void ldsm4(uint32_t a, uint32_t* r) {
    asm volatile("ldmatrix.sync.aligned.m8n8.x4.shared.b16 {%0,%1,%2,%3}, [%4];"
                 : "=r"(r[0]), "=r"(r[1]), "=r"(r[2]), "=r"(r[3]) : "r"(a));
}
__device__ __forceinline__ void ldsm4t(uint32_t a, uint32_t* r) {
    asm volatile("ldmatrix.sync.aligned.m8n8.x4.trans.shared.b16 {%0,%1,%2,%3}, [%4];"
                 : "=r"(r[0]), "=r"(r[1]), "=r"(r[2]), "=r"(r[3]) : "r"(a));
}
__device__ __forceinline__ void mma16816(float* d, const uint32_t* a, const uint32_t* b) {
    asm volatile(
        "mma.sync.aligned.m16n8k16.row.col.f32.bf16.bf16.f32 "
        "{%0,%1,%2,%3},{%4,%5,%6,%7},{%8,%9},{%0,%1,%2,%3};"
        : "+f"(d[0]), "+f"(d[1]), "+f"(d[2]), "+f"(d[3])
        : "r"(a[0]), "r"(a[1]), "r"(a[2]), "r"(a[3]), "r"(b[0]), "r"(b[1]));
}
__device__ __forceinline__ float gelu_exact(float v) {
    return 0.5f * v * (1.0f + erff(v * 0.70710678118654752f));
}
__device__ __forceinline__ void split_bf(float v, bf16& h, bf16& l) {
    h = __float2bfloat16(v);
    l = __float2bfloat16(v - __bfloat162float(h));
}
__device__ __forceinline__ uint32_t pack_bf(bf16 a, bf16 b) {
    return (uint32_t)__bfloat16_as_ushort(a) | ((uint32_t)__bfloat16_as_ushort(b) << 16);
}

// ---------------- prep -------------------------------------------------------
__global__ void prep_basis() {
    int n = blockIdx.x * 256 + threadIdx.x;
    if (n >= NN) return;
#pragma unroll
    for (int m = 0; m < MODES; m++) {
        int r = (m * n) & (NN - 1);
        float tf = 2.0f * (float)r / (float)NN;
        float s, c;
        sincospif(tf, &s, &c);
        bf16 h, l;
        split_bf(c, h, l);
        g_basDH[(size_t)(2 * m) * NN + n] = h;
        g_basDL[(size_t)(2 * m) * NN + n] = l;
        split_bf(s, h, l);
        g_basDH[(size_t)(2 * m + 1) * NN + n] = h;
        g_basDL[(size_t)(2 * m + 1) * NN + n] = l;
    }
}

__global__ void prep_w(const float* __restrict__ cw, const float* __restrict__ w1) {
    int idx = blockIdx.x * 256 + threadIdx.x;
    if (idx < 4 * 64 * 64) {
        bf16 h, l;
        split_bf(cw[idx], h, l);
        g_cwH[idx] = h; g_cwL[idx] = l;
    } else if (idx < 4 * 64 * 64 + 128 * 64) {
        int i2 = idx - 4 * 64 * 64;
        int c = i2 >> 7, j = i2 & 127;
        bf16 h, l;
        split_bf(w1[c * 128 + j], h, l);
        g_w1TH[j * 64 + c] = h; g_w1TL[j * 64 + c] = l;
    }
}

// ---------------- DFT MMA core (8 warps) -------------------------------------
__device__ __forceinline__ void dft_core8(uint32_t sb, int VHo, int VLo, int BHo, int BLo,
                                          int wid, int lane, size_t pfbase) {
    int lr = lane & 7, li = lane >> 3;
    int drA = (li & 1) * 8, dcA = (li >> 1) * 16;
    int jt = (wid & 1) * 16;
    int cb2 = (wid >> 1) * 32;
    float f[2][4];
#pragma unroll
    for (int i = 0; i < 2; i++)
#pragma unroll
        for (int k = 0; k < 4; k++) f[i][k] = 0.0f;

#pragma unroll
    for (int s = 0; s < 8; s++) {
        int half = s >> 2, kb = (s & 3) * 32;
        uint32_t ah[4], al[4], bh[4], bl[4];
        ldsm4(sb + BHo + half * 4096 + SWZ((jt + drA + lr) * 128 + kb + dcA), ah);
        ldsm4(sb + BLo + half * 4096 + SWZ((jt + drA + lr) * 128 + kb + dcA), al);
        ldsm4t(sb + VHo + SWZ((16 * s + drA + lr) * 128 + cb2 + dcA), bh);
        ldsm4t(sb + VLo + SWZ((16 * s + drA + lr) * 128 + cb2 + dcA), bl);
        mma16816(f[0], ah, bh); mma16816(f[1], ah, bh + 2);
        mma16816(f[0], al, bh); mma16816(f[1], al, bh + 2);
        mma16816(f[0], ah, bl); mma16816(f[1], ah, bl + 2);
    }
    int q = lane & 3, g = lane >> 2;
    int cbase = (wid >> 1) * 16;
#pragma unroll
    for (int i = 0; i < 2; i++) {
        int c = cbase + i * 8 + 2 * q;
        int j = jt + g;
        *(float2*)&g_pF[(pfbase + j) * 64 + c]     = make_float2(f[i][0], f[i][1]);
        *(float2*)&g_pF[(pfbase + j + 8) * 64 + c] = make_float2(f[i][2], f[i][3]);
    }
}

// ---------------- fused fc0 + DFT --------------------------------------------
#define F0_VH 0
#define F0_VL 16384
#define F0_BH 32768
#define F0_BL 40960
#define F0_W0 49152
#define F0_SZ 50176

__global__ __launch_bounds__(256, 3)
void fc0dft_kernel(const float* __restrict__ xg, const float* __restrict__ tg,
                   const float* __restrict__ w0, const float* __restrict__ b0) {
    extern __shared__ char smc[];
    uint32_t sb = smem_u32(smc);
    float* w0s = (float*)(smc + F0_W0);
    float* b0s = w0s + 128;
    int tid = threadIdx.x, wid = tid >> 5, lane = tid & 31;
    int b = blockIdx.y, n0 = blockIdx.x * NT;

    if (tid < 128) w0s[tid] = w0[tid];
    if (tid < 64)  b0s[tid] = b0[tid];
    for (int i = tid; i < 512; i += 256) {
        int half = i >> 8, rest = i & 255, j = rest >> 3, q = rest & 7;
        uint32_t so = half * 4096 + SWZ(j * 128 + q * 16);
        *(uint4*)(smc + F0_BH + so) = ((const uint4*)(g_basDH + (size_t)j * NN + n0 + half * 64))[q];
        *(uint4*)(smc + F0_BL + so) = ((const uint4*)(g_basDL + (size_t)j * NN + n0 + half * 64))[q];
    }
    __syncthreads();

    int n = tid >> 1, c0 = (tid & 1) * 32;
    float xv = xg[(size_t)b * NN + n0 + n], tv = tg[(size_t)b * NN + n0 + n];
    uint32_t hw[16], lw[16];
#pragma unroll
    for (int k = 0; k < 16; k++) {
        int c = c0 + 2 * k;
        float v0 = fmaf(w0s[c],     xv, fmaf(w0s[64 + c],     tv, b0s[c]));
        float v1 = fmaf(w0s[c + 1], xv, fmaf(w0s[64 + c + 1], tv, b0s[c + 1]));
        bf16 h0, l0, h1, l1;
        split_bf(v0, h0, l0);
        split_bf(v1, h1, l1);
        hw[k] = pack_bf(h0, h1);
        lw[k] = pack_bf(l0, l1);
    }
    size_t ro = ((size_t)b * NN + n0 + n) * 64 + c0;
#pragma unroll
    for (int g4 = 0; g4 < 4; g4++) {
        uint4 hv = make_uint4(hw[4 * g4], hw[4 * g4 + 1], hw[4 * g4 + 2], hw[4 * g4 + 3]);
        uint4 lv = make_uint4(lw[4 * g4], lw[4 * g4 + 1], lw[4 * g4 + 2], lw[4 * g4 + 3]);
        *(uint4*)(g_hH0 + ro + 8 * g4) = hv;
        *(uint4*)(g_hL0 + ro + 8 * g4) = lv;
        uint32_t so = SWZ(n * 128 + c0 * 2 + g4 * 16);
        *(uint4*)(smc + F0_VH + so) = hv;
        *(uint4*)(smc + F0_VL + so) = lv;
    }
    __syncthreads();
    dft_core8(sb, F0_VH, F0_VL, F0_BH, F0_BL, wid, lane,
              ((size_t)b * TBC + blockIdx.x) * J2);
}

// ---------------- reduce (wide grid) + modemix -------------------------------
__global__ __launch_bounds__(256)
void reduce_kernel() {
    int b = blockIdx.x;
    int idx = blockIdx.y * 256 + threadIdx.x;     // (j,c) index
    const float* p = &g_pF[(size_t)b * TBC * 2048 + idx];
    float s = 0.0f;
#pragma unroll 8
    for (int ch = 0; ch < TBC; ch++) s += p[(size_t)ch * 2048];
    g_F[(size_t)b * 2048 + idx] = s;
}

__global__ __launch_bounds__(1024)
void modemix_kernel(const float* __restrict__ swr,
                    const float* __restrict__ swi) {
    __shared__ float fs[64 * 33];   // [c][j]
    int b = blockIdx.x, tid = threadIdx.x;
    for (int idx = tid; idx < 2048; idx += 1024) {
        int j = idx >> 6, c = idx & 63;
        fs[c * 33 + j] = g_F[(size_t)b * 2048 + idx];
    }
    __syncthreads();
    int m = tid & 15, o = tid >> 4;
    float re = 0.0f, im = 0.0f;
    for (int i = 0; i < 64; i++) {
        float fr = fs[i * 33 + 2 * m];
        float fn = fs[i * 33 + 2 * m + 1];
        float wr = swr[(i * 64 + o) * 16 + m];
        float wi = swi[(i * 64 + o) * 16 + m];
        re = fmaf(fr, wr, fmaf(fn, wi, re));
        im = fmaf(fr, wi, fmaf(-fn, wr, im));
    }
    float cm = (m == 0 ? 1.0f : 2.0f) / (float)NN;
    float g0 = cm * re;
    float g1 = -cm * im;
    size_t r = ((size_t)b * 64 + o) * 64;
    bf16 h, l;
    split_bf(g0, h, l);
    g_GpP[r + 2 * m] = h;      g_GpP[r + 32 + 2 * m] = l;
    split_bf(g1, h, l);
    g_GpP[r + 2 * m + 1] = h;  g_GpP[r + 32 + 2 * m + 1] = l;
}

// ---------------- fused layer: conv + synthesis (+gelu) (+DFT) ----------------
#define MM_HH  0
#define MM_HL  16384
#define MM_WH  32768
#define MM_WL  40960
#define MM_BDH 49152
#define MM_BDL 57344
#define MM_G   65536
#define MM_CB  73728
#define MM_SZ  73984

template <bool GELU, bool DFT>
__global__ __launch_bounds__(256, 3)
void mma_layer(int dir, int layer, int rev, const float* __restrict__ cb_all) {
    extern __shared__ char smc[];
    uint32_t sb = smem_u32(smc);
    int tid = threadIdx.x, wid = tid >> 5, lane = tid & 31;
    // serpentine traversal: alternate layers reverse (b, chunk) so this
    // layer's first reads hit the previous layer's last (L2-hot) writes
    int b   = rev ? (BB - 1 - (int)blockIdx.y) : (int)blockIdx.y;
    int chk = rev ? (TBC - 1 - (int)blockIdx.x) : (int)blockIdx.x;
    int n0 = chk * NT;

    const bf16* hHsrc = (dir ? g_hH1 : g_hH0) + ((size_t)b * NN + n0) * 64;
    const bf16* hLsrc = (dir ? g_hL1 : g_hL0) + ((size_t)b * NN + n0) * 64;
    bf16* hHdst = (dir ? g_hH0 : g_hH1) + ((size_t)b * NN + n0) * 64;
    bf16* hLdst = (dir ? g_hL0 : g_hL1) + ((size_t)b * NN + n0) * 64;

    for (int i = tid; i < 1024; i += 256) {
        int r = i >> 3, q = i & 7;
        uint32_t so = SWZ(r * 128 + q * 16);
        *(uint4*)(smc + MM_HH + so) = ((const uint4*)(hHsrc + (size_t)r * 64))[q];
        *(uint4*)(smc + MM_HL + so) = ((const uint4*)(hLsrc + (size_t)r * 64))[q];
    }
    for (int i = tid; i < 512; i += 256) {
        int r = i >> 3, q = i & 7;
        uint32_t so = SWZ(r * 128 + q * 16);
        *(uint4*)(smc + MM_WH + so) = ((const uint4*)(g_cwH + (size_t)(layer * 64 + r) * 64))[q];
        *(uint4*)(smc + MM_WL + so) = ((const uint4*)(g_cwL + (size_t)(layer * 64 + r) * 64))[q];
        *(uint4*)(smc + MM_G  + so) = ((const uint4*)(g_GpP + ((size_t)b * 64 + r) * 64))[q];
        int half = i >> 8, rest = i & 255, j = rest >> 3, qq = rest & 7;
        uint32_t so2 = half * 4096 + SWZ(j * 128 + qq * 16);
        *(uint4*)(smc + MM_BDH + so2) = ((const uint4*)(g_basDH + (size_t)j * NN + n0 + half * 64))[qq];
        *(uint4*)(smc + MM_BDL + so2) = ((const uint4*)(g_basDL + (size_t)j * NN + n0 + half * 64))[qq];
    }
    if (tid < 64) ((float*)(smc + MM_CB))[tid] = cb_all[layer * 64 + tid];
    __syncthreads();

    int lr = lane & 7, li = lane >> 3;
    int drA = (li & 1) * 8, dcA = (li >> 1) * 16;
    int drB = (li >> 1) * 8, dcB = (li & 1) * 16;
    int rA0 = 16 * wid;

    float acc[8][4];
#pragma unroll
    for (int nt = 0; nt < 8; nt++)
#pragma unroll
        for (int k = 0; k < 4; k++) acc[nt][k] = 0.0f;

    // conv: (Hh+Hl)(Wh+Wl) 3-term
#pragma unroll
    for (int s = 0; s < 4; s++) {
        int kb = s * 32;
        uint32_t ah[4], al[4];
        ldsm4(sb + MM_HH + SWZ((rA0 + drA + lr) * 128 + kb + dcA), ah);
        ldsm4(sb + MM_HL + SWZ((rA0 + drA + lr) * 128 + kb + dcA), al);
#pragma unroll
        for (int np = 0; np < 4; np++) {
            uint32_t bb[4];
            ldsm4(sb + MM_WH + SWZ((np * 16 + drB + lr) * 128 + kb + dcB), bb);
            mma16816(acc[2 * np],     ah, bb);
            mma16816(acc[2 * np + 1], ah, bb + 2);
            mma16816(acc[2 * np],     al, bb);
            mma16816(acc[2 * np + 1], al, bb + 2);
            ldsm4(sb + MM_WL + SWZ((np * 16 + drB + lr) * 128 + kb + dcB), bb);
            mma16816(acc[2 * np],     ah, bb);
            mma16816(acc[2 * np + 1], ah, bb + 2);
        }
    }
    // synthesis: A = trans(basD half tile), B = packed G
    {
        int halfS = rA0 >> 6;
        int colA = (rA0 & 63) * 2 + (li & 1) * 16;
        int rowA = (li >> 1) * 8 + lr;
#pragma unroll
        for (int s = 0; s < 2; s++) {
            int kb = s * 32;
            uint32_t ah[4], al[4];
            ldsm4t(sb + MM_BDH + halfS * 4096 + SWZ((s * 16 + rowA) * 128 + colA), ah);
            ldsm4t(sb + MM_BDL + halfS * 4096 + SWZ((s * 16 + rowA) * 128 + colA), al);
#pragma unroll
            for (int np = 0; np < 4; np++) {
                uint32_t bb[4];
                ldsm4(sb + MM_G + SWZ((np * 16 + drB + lr) * 128 + kb + dcB), bb);
                mma16816(acc[2 * np],     ah, bb);
                mma16816(acc[2 * np + 1], ah, bb + 2);
                mma16816(acc[2 * np],     al, bb);
                mma16816(acc[2 * np + 1], al, bb + 2);
                ldsm4(sb + MM_G + SWZ((np * 16 + drB + lr) * 128 + 64 + kb + dcB), bb);
                mma16816(acc[2 * np],     ah, bb);
                mma16816(acc[2 * np + 1], ah, bb + 2);
            }
        }
    }
    __syncthreads();

    // epilogue: bias + gelu, write vH/vL into HH/HL
    int q = lane & 3, g = lane >> 2;
    const float* cbs = (const float*)(smc + MM_CB);
#pragma unroll
    for (int nt = 0; nt < 8; nt++) {
        int o0 = nt * 8 + 2 * q;
        int r0 = 16 * wid + g;
        float v0 = acc[nt][0] + cbs[o0];
        float v1 = acc[nt][1] + cbs[o0 + 1];
        float v2 = acc[nt][2] + cbs[o0];
        float v3 = acc[nt][3] + cbs[o0 + 1];
        if (GELU) {
            v0 = gelu_exact(v0); v1 = gelu_exact(v1);
            v2 = gelu_exact(v2); v3 = gelu_exact(v3);
        }
        bf16 h0, l0, h1, l1;
        split_bf(v0, h0, l0); split_bf(v1, h1, l1);
        *(uint32_t*)(smc + MM_HH + SWZ(r0 * 128 + o0 * 2)) = pack_bf(h0, h1);
        *(uint32_t*)(smc + MM_HL + SWZ(r0 * 128 + o0 * 2)) = pack_bf(l0, l1);
        split_bf(v2, h0, l0); split_bf(v3, h1, l1);
        *(uint32_t*)(smc + MM_HH + SWZ((r0 + 8) * 128 + o0 * 2)) = pack_bf(h0, h1);
        *(uint32_t*)(smc + MM_HL + SWZ((r0 + 8) * 128 + o0 * 2)) = pack_bf(l0, l1);
    }
    __syncthreads();

    for (int i = tid; i < 1024; i += 256) {
        int r = i >> 3, qq = i & 7;
        uint32_t so = SWZ(r * 128 + qq * 16);
        ((uint4*)(hHdst + (size_t)r * 64))[qq] = *(uint4*)(smc + MM_HH + so);
        ((uint4*)(hLdst + (size_t)r * 64))[qq] = *(uint4*)(smc + MM_HL + so);
    }
    if (DFT) {
        dft_core8(sb, MM_HH, MM_HL, MM_BDH, MM_BDL, wid, lane,
                  ((size_t)b * TBC + chk) * J2);
    }
}

// ---------------- fc1 + gelu + fc2 via MMA -----------------------------------
#define FC_HH 0
#define FC_HL 16384
#define FC_WH 32768
#define FC_WL 49152
#define FC_B1 65536
#define FC_W2 66048
#define FC_SZ 66560

__global__ __launch_bounds__(256, 2)
void fc12_kernel(const float* __restrict__ b1, const float* __restrict__ w2,
                 const float* __restrict__ b2, float* __restrict__ out) {
    extern __shared__ char smc[];
    uint32_t sb = smem_u32(smc);
    int tid = threadIdx.x, wid = tid >> 5, lane = tid & 31;
    // reversed traversal (layer 3 ran forward)
    int b = BB - 1 - (int)blockIdx.y;
    int n0 = (TBC - 1 - (int)blockIdx.x) * NT;

    const bf16* hH = g_hH0 + ((size_t)b * NN + n0) * 64;
    const bf16* hL = g_hL0 + ((size_t)b * NN + n0) * 64;
    for (int i = tid; i < 1024; i += 256) {
        int r = i >> 3, q = i & 7;
        uint32_t so = SWZ(r * 128 + q * 16);
        *(uint4*)(smc + FC_HH + so) = ((const uint4*)(hH + (size_t)r * 64))[q];
        *(uint4*)(smc + FC_HL + so) = ((const uint4*)(hL + (size_t)r * 64))[q];
        *(uint4*)(smc + FC_WH + so) = ((const uint4*)(g_w1TH + (size_t)r * 64))[q];
        *(uint4*)(smc + FC_WL + so) = ((const uint4*)(g_w1TL + (size_t)r * 64))[q];
    }
    if (tid < 128) {
        ((float*)(smc + FC_B1))[tid] = b1[tid];
        ((float*)(smc + FC_W2))[tid] = w2[tid];
    }
    __syncthreads();

    int lr = lane & 7, li = lane >> 3;
    int drA = (li & 1) * 8, dcA = (li >> 1) * 16;
    int drB = (li >> 1) * 8, dcB = (li & 1) * 16;
    int rA0 = 16 * wid;

    float acc[16][4];
#pragma unroll
    for (int nt = 0; nt < 16; nt++)
#pragma unroll
        for (int k = 0; k < 4; k++) acc[nt][k] = 0.0f;

#pragma unroll
    for (int s = 0; s < 4; s++) {
        int kb = s * 32;
        uint32_t ah[4], al[4];
        ldsm4(sb + FC_HH + SWZ((rA0 + drA + lr) * 128 + kb + dcA), ah);
        ldsm4(sb + FC_HL + SWZ((rA0 + drA + lr) * 128 + kb + dcA), al);
#pragma unroll
        for (int np = 0; np < 8; np++) {
            uint32_t bb[4];
            ldsm4(sb + FC_WH + SWZ((np * 16 + drB + lr) * 128 + kb + dcB), bb);
            mma16816(acc[2 * np],     ah, bb);
            mma16816(acc[2 * np + 1], ah, bb + 2);
            mma16816(acc[2 * np],     al, bb);
            mma16816(acc[2 * np + 1], al, bb + 2);
            ldsm4(sb + FC_WL + SWZ((np * 16 + drB + lr) * 128 + kb + dcB), bb);
            mma16816(acc[2 * np],     ah, bb);
            mma16816(acc[2 * np + 1], ah, bb + 2);
        }
    }

    int q = lane & 3, g = lane >> 2;
    const float* b1s = (const float*)(smc + FC_B1);
    const float* w2s = (const float*)(smc + FC_W2);
    float s0 = 0.0f, s1 = 0.0f;
#pragma unroll
    for (int nt = 0; nt < 16; nt++) {
        int j0 = nt * 8 + 2 * q;
        s0 = fmaf(w2s[j0],     gelu_exact(acc[nt][0] + b1s[j0]),     s0);
        s0 = fmaf(w2s[j0 + 1], gelu_exact(acc[nt][1] + b1s[j0 + 1]), s0);
        s1 = fmaf(w2s[j0],     gelu_exact(acc[nt][2] + b1s[j0]),     s1);
        s1 = fmaf(w2s[j0 + 1], gelu_exact(acc[nt][3] + b1s[j0 + 1]), s1);
    }
    s0 += __shfl_xor_sync(0xffffffffu, s0, 1);
    s0 += __shfl_xor_sync(0xffffffffu, s0, 2);
    s1 += __shfl_xor_sync(0xffffffffu, s1, 1);
    s1 += __shfl_xor_sync(0xffffffffu, s1, 2);
    if (q == 0) {
        float bv = b2[0];
        out[(size_t)b * NN + n0 + 16 * wid + g]     = s0 + bv;
        out[(size_t)b * NN + n0 + 16 * wid + g + 8] = s1 + bv;
    }
}

// ---------------- host launcher ----------------------------------------------
extern "C" void kernel_launch(void* const* d_in, const int* in_sizes, int n_in,
                              void* d_out, int out_size) {
    const float* x    = (const float*)d_in[0];
    const float* t    = (const float*)d_in[1];
    const float* fc0w = (const float*)d_in[2];
    const float* fc0b = (const float*)d_in[3];
    const float* swr  = (const float*)d_in[4];
    const float* swi  = (const float*)d_in[5];
    const float* cw   = (const float*)d_in[6];
    const float* cb   = (const float*)d_in[7];
    const float* w1   = (const float*)d_in[8];
    const float* b1   = (const float*)d_in[9];
    const float* w2   = (const float*)d_in[10];
    const float* b2   = (const float*)d_in[11];
    float* out = (float*)d_out;

    cudaFuncSetAttribute(mma_layer<true,  true >, cudaFuncAttributeMaxDynamicSharedMemorySize, MM_SZ);
    cudaFuncSetAttribute(mma_layer<false, false>, cudaFuncAttributeMaxDynamicSharedMemorySize, MM_SZ);
    cudaFuncSetAttribute(fc0dft_kernel, cudaFuncAttributeMaxDynamicSharedMemorySize, F0_SZ);
    cudaFuncSetAttribute(fc12_kernel, cudaFuncAttributeMaxDynamicSharedMemorySize, FC_SZ);

    dim3 g(TBC, BB);
    dim3 gr(BB, 8);
    prep_basis<<<NN / 256, 256>>>();
    prep_w<<<(4 * 4096 + 128 * 64 + 255) / 256, 256>>>(cw, w1);

    fc0dft_kernel<<<g, 256, F0_SZ>>>(x, t, fc0w, fc0b);   // forward

    const size_t SWL = (size_t)64 * 64 * 16;
    reduce_kernel<<<gr, 256>>>();
    modemix_kernel<<<BB, 1024>>>(swr + 0 * SWL, swi + 0 * SWL);
    mma_layer<true, true><<<g, 256, MM_SZ>>>(0, 0, 1, cb);   // reversed

    reduce_kernel<<<gr, 256>>>();
    modemix_kernel<<<BB, 1024>>>(swr + 1 * SWL, swi + 1 * SWL);
    mma_layer<true, true><<<g, 256, MM_SZ>>>(1, 1, 0, cb);   // forward

    reduce_kernel<<<gr, 256>>>();
    modemix_kernel<<<BB, 1024>>>(swr + 2 * SWL, swi + 2 * SWL);
    mma_layer<true, true><<<g, 256, MM_SZ>>>(0, 2, 1, cb);   // reversed

    reduce_kernel<<<gr, 256>>>();
    modemix_kernel<<<BB, 1024>>>(swr + 3 * SWL, swi + 3 * SWL);
    mma_layer<false, false><<<g, 256, MM_SZ>>>(1, 3, 0, cb); // forward

    fc12_kernel<<<g, 256, FC_SZ>>>(b1, w2, b2, out);         // reversed
}

// round 11
// speedup vs baseline: 4.1062x; 1.0730x over previous
#include <cuda_runtime.h>
#include <cuda_bf16.h>
#include <math.h>
#include <stdint.h>
#include <stddef.h>

#define BB 64
#define NN 8192
#define MODES 16
#define J2 32
#define NT 128
#define TBC (NN / NT)

typedef __nv_bfloat16 bf16;

// ---------------- device scratch --------------------------------------------
__device__ bf16  g_hH0[(size_t)BB * NN * 64];
__device__ bf16  g_hL0[(size_t)BB * NN * 64];
__device__ bf16  g_hH1[(size_t)BB * NN * 64];
__device__ bf16  g_hL1[(size_t)BB * NN * 64];
__device__ float g_pF[(size_t)BB * TBC * J2 * 64];    // [b][chunk][j][c]
__device__ float g_F[(size_t)BB * J2 * 64];           // [b][j][c]
__device__ bf16  g_basDH[(size_t)J2 * NN];            // [j][n] hi
__device__ bf16  g_basDL[(size_t)J2 * NN];            // [j][n] lo
__device__ bf16  g_cwH[4 * 64 * 64];                  // [l][o][c]
__device__ bf16  g_cwL[4 * 64 * 64];
__device__ bf16  g_GpP[(size_t)BB * 64 * 64];         // [b][o][ gh(32) | gl(32) ]
__device__ bf16  g_w1TH[128 * 64];                    // [j][c]
__device__ bf16  g_w1TL[128 * 64];

// ---------------- helpers ----------------------------------------------------
#define SWZ(x) ((x) ^ (((x) >> 3) & 0x70))

__device__ __forceinline__ uint32_t smem_u32(const void* p) {
    uint32_t a;
    asm("{ .reg .u64 t; cvta.to.shared.u64 t, %1; cvt.u32.u64 %0, t; }" : "=r"(a) : "l"(p));
    return a;
}
__device__ __forceinline__ void cpa16(uint32_t dst, const void* src) {
    asm volatile("cp.async.cg.shared.global [%0], [%1], 16;" :: "r"(dst), "l"(src));
}
#define CPA_COMMIT() asm volatile("cp.async.commit_group;" ::: "memory")
#define CPA_WAIT(n)  asm volatile("cp.async.wait_group %0;" :: "n"(n) : "memory")

__device__ __forceinline__ void ldsm4(uint32_t a, uint32_t* r) {
    asm volatile("ldmatrix.sync.aligned.m8n8.x4.shared.b16 {%0,%1,%2,%3}, [%4];"
                 : "=r"(r[0]), "=r"(r[1]), "=r"(r[2]), "=r"(r[3]) : "r"(a));
}
__device__ __forceinline__ void ldsm4t(uint32_t a, uint32_t* r) {
    asm volatile("ldmatrix.sync.aligned.m8n8.x4.trans.shared.b16 {%0,%1,%2,%3}, [%4];"
                 : "=r"(r[0]), "=r"(r[1]), "=r"(r[2]), "=r"(r[3]) : "r"(a));
}
__device__ __forceinline__ void mma16816(float* d, const uint32_t* a, const uint32_t* b) {
    asm volatile(
        "mma.sync.aligned.m16n8k16.row.col.f32.bf16.bf16.f32 "
        "{%0,%1,%2,%3},{%4,%5,%6,%7},{%8,%9},{%0,%1,%2,%3};"
        : "+f"(d[0]), "+f"(d[1]), "+f"(d[2]), "+f"(d[3])
        : "r"(a[0]), "r"(a[1]), "r"(a[2]), "r"(a[3]), "r"(b[0]), "r"(b[1]));
}
__device__ __forceinline__ float gelu_exact(float v) {
    return 0.5f * v * (1.0f + erff(v * 0.70710678118654752f));
}
__device__ __forceinline__ void split_bf(float v, bf16& h, bf16& l) {
    h = __float2bfloat16(v);
    l = __float2bfloat16(v - __bfloat162float(h));
}
__device__ __forceinline__ uint32_t pack_bf(bf16 a, bf16 b) {
    return (uint32_t)__bfloat16_as_ushort(a) | ((uint32_t)__bfloat16_as_ushort(b) << 16);
}

// ---------------- prep -------------------------------------------------------
__global__ void prep_basis() {
    int n = blockIdx.x * 256 + threadIdx.x;
    if (n >= NN) return;
#pragma unroll
    for (int m = 0; m < MODES; m++) {
        int r = (m * n) & (NN - 1);
        float tf = 2.0f * (float)r / (float)NN;
        float s, c;
        sincospif(tf, &s, &c);
        bf16 h, l;
        split_bf(c, h, l);
        g_basDH[(size_t)(2 * m) * NN + n] = h;
        g_basDL[(size_t)(2 * m) * NN + n] = l;
        split_bf(s, h, l);
        g_basDH[(size_t)(2 * m + 1) * NN + n] = h;
        g_basDL[(size_t)(2 * m + 1) * NN + n] = l;
    }
}

__global__ void prep_w(const float* __restrict__ cw, const float* __restrict__ w1) {
    int idx = blockIdx.x * 256 + threadIdx.x;
    if (idx < 4 * 64 * 64) {
        bf16 h, l;
        split_bf(cw[idx], h, l);
        g_cwH[idx] = h; g_cwL[idx] = l;
    } else if (idx < 4 * 64 * 64 + 128 * 64) {
        int i2 = idx - 4 * 64 * 64;
        int c = i2 >> 7, j = i2 & 127;
        bf16 h, l;
        split_bf(w1[c * 128 + j], h, l);
        g_w1TH[j * 64 + c] = h; g_w1TL[j * 64 + c] = l;
    }
}

// ---------------- DFT MMA core (8 warps) -------------------------------------
__device__ __forceinline__ void dft_core8(uint32_t sb, int VHo, int VLo, int BHo, int BLo,
                                          int wid, int lane, size_t pfbase) {
    int lr = lane & 7, li = lane >> 3;
    int drA = (li & 1) * 8, dcA = (li >> 1) * 16;
    int jt = (wid & 1) * 16;
    int cb2 = (wid >> 1) * 32;
    float f[2][4];
#pragma unroll
    for (int i = 0; i < 2; i++)
#pragma unroll
        for (int k = 0; k < 4; k++) f[i][k] = 0.0f;

#pragma unroll
    for (int s = 0; s < 8; s++) {
        int half = s >> 2, kb = (s & 3) * 32;
        uint32_t ah[4], al[4], bh[4], bl[4];
        ldsm4(sb + BHo + half * 4096 + SWZ((jt + drA + lr) * 128 + kb + dcA), ah);
        ldsm4(sb + BLo + half * 4096 + SWZ((jt + drA + lr) * 128 + kb + dcA), al);
        ldsm4t(sb + VHo + SWZ((16 * s + drA + lr) * 128 + cb2 + dcA), bh);
        ldsm4t(sb + VLo + SWZ((16 * s + drA + lr) * 128 + cb2 + dcA), bl);
        mma16816(f[0], ah, bh); mma16816(f[1], ah, bh + 2);
        mma16816(f[0], al, bh); mma16816(f[1], al, bh + 2);
        mma16816(f[0], ah, bl); mma16816(f[1], ah, bl + 2);
    }
    int q = lane & 3, g = lane >> 2;
    int cbase = (wid >> 1) * 16;
#pragma unroll
    for (int i = 0; i < 2; i++) {
        int c = cbase + i * 8 + 2 * q;
        int j = jt + g;
        *(float2*)&g_pF[(pfbase + j) * 64 + c]     = make_float2(f[i][0], f[i][1]);
        *(float2*)&g_pF[(pfbase + j + 8) * 64 + c] = make_float2(f[i][2], f[i][3]);
    }
}

// ---------------- fused fc0 + DFT --------------------------------------------
#define F0_VH 0
#define F0_VL 16384
#define F0_BH 32768
#define F0_BL 40960
#define F0_W0 49152
#define F0_SZ 50176

__global__ __launch_bounds__(256, 3)
void fc0dft_kernel(const float* __restrict__ xg, const float* __restrict__ tg,
                   const float* __restrict__ w0, const float* __restrict__ b0) {
    extern __shared__ char smc[];
    uint32_t sb = smem_u32(smc);
    float* w0s = (float*)(smc + F0_W0);
    float* b0s = w0s + 128;
    int tid = threadIdx.x, wid = tid >> 5, lane = tid & 31;
    int b = blockIdx.y, n0 = blockIdx.x * NT;

    // basD via cp.async — waited only after fc0 compute
    for (int i = tid; i < 512; i += 256) {
        int half = i >> 8, rest = i & 255, j = rest >> 3, q = rest & 7;
        uint32_t so = half * 4096 + SWZ(j * 128 + q * 16);
        cpa16(sb + F0_BH + so, (const uint4*)(g_basDH + (size_t)j * NN + n0 + half * 64) + q);
        cpa16(sb + F0_BL + so, (const uint4*)(g_basDL + (size_t)j * NN + n0 + half * 64) + q);
    }
    CPA_COMMIT();
    if (tid < 128) w0s[tid] = w0[tid];
    if (tid < 64)  b0s[tid] = b0[tid];
    __syncthreads();

    int n = tid >> 1, c0 = (tid & 1) * 32;
    float xv = xg[(size_t)b * NN + n0 + n], tv = tg[(size_t)b * NN + n0 + n];
    uint32_t hw[16], lw[16];
#pragma unroll
    for (int k = 0; k < 16; k++) {
        int c = c0 + 2 * k;
        float v0 = fmaf(w0s[c],     xv, fmaf(w0s[64 + c],     tv, b0s[c]));
        float v1 = fmaf(w0s[c + 1], xv, fmaf(w0s[64 + c + 1], tv, b0s[c + 1]));
        bf16 h0, l0, h1, l1;
        split_bf(v0, h0, l0);
        split_bf(v1, h1, l1);
        hw[k] = pack_bf(h0, h1);
        lw[k] = pack_bf(l0, l1);
    }
    size_t ro = ((size_t)b * NN + n0 + n) * 64 + c0;
#pragma unroll
    for (int g4 = 0; g4 < 4; g4++) {
        uint4 hv = make_uint4(hw[4 * g4], hw[4 * g4 + 1], hw[4 * g4 + 2], hw[4 * g4 + 3]);
        uint4 lv = make_uint4(lw[4 * g4], lw[4 * g4 + 1], lw[4 * g4 + 2], lw[4 * g4 + 3]);
        *(uint4*)(g_hH0 + ro + 8 * g4) = hv;
        *(uint4*)(g_hL0 + ro + 8 * g4) = lv;
        uint32_t so = SWZ(n * 128 + c0 * 2 + g4 * 16);
        *(uint4*)(smc + F0_VH + so) = hv;
        *(uint4*)(smc + F0_VL + so) = lv;
    }
    CPA_WAIT(0);
    __syncthreads();
    dft_core8(sb, F0_VH, F0_VL, F0_BH, F0_BL, wid, lane,
              ((size_t)b * TBC + blockIdx.x) * J2);
}

// ---------------- reduce (wide grid) + modemix -------------------------------
__global__ __launch_bounds__(256)
void reduce_kernel() {
    int b = blockIdx.x;
    int idx = blockIdx.y * 256 + threadIdx.x;
    const float* p = &g_pF[(size_t)b * TBC * 2048 + idx];
    float s = 0.0f;
#pragma unroll 8
    for (int ch = 0; ch < TBC; ch++) s += p[(size_t)ch * 2048];
    g_F[(size_t)b * 2048 + idx] = s;
}

__global__ __launch_bounds__(1024)
void modemix_kernel(const float* __restrict__ swr,
                    const float* __restrict__ swi) {
    __shared__ float fs[64 * 33];   // [c][j]
    int b = blockIdx.x, tid = threadIdx.x;
    for (int idx = tid; idx < 2048; idx += 1024) {
        int j = idx >> 6, c = idx & 63;
        fs[c * 33 + j] = g_F[(size_t)b * 2048 + idx];
    }
    __syncthreads();
    int m = tid & 15, o = tid >> 4;
    float re = 0.0f, im = 0.0f;
    for (int i = 0; i < 64; i++) {
        float fr = fs[i * 33 + 2 * m];
        float fn = fs[i * 33 + 2 * m + 1];
        float wr = swr[(i * 64 + o) * 16 + m];
        float wi = swi[(i * 64 + o) * 16 + m];
        re = fmaf(fr, wr, fmaf(fn, wi, re));
        im = fmaf(fr, wi, fmaf(-fn, wr, im));
    }
    float cm = (m == 0 ? 1.0f : 2.0f) / (float)NN;
    float g0 = cm * re;
    float g1 = -cm * im;
    size_t r = ((size_t)b * 64 + o) * 64;
    bf16 h, l;
    split_bf(g0, h, l);
    g_GpP[r + 2 * m] = h;      g_GpP[r + 32 + 2 * m] = l;
    split_bf(g1, h, l);
    g_GpP[r + 2 * m + 1] = h;  g_GpP[r + 32 + 2 * m + 1] = l;
}

// ---------------- fused layer: conv + synthesis (+gelu) (+DFT) ----------------
#define MM_HH  0
#define MM_HL  16384
#define MM_WH  32768
#define MM_WL  40960
#define MM_BDH 49152
#define MM_BDL 57344
#define MM_G   65536
#define MM_CB  73728
#define MM_SZ  73984

template <bool GELU, bool DFT>
__global__ __launch_bounds__(256, 3)
void mma_layer(int dir, int layer, int rev, const float* __restrict__ cb_all) {
    extern __shared__ char smc[];
    uint32_t sb = smem_u32(smc);
    int tid = threadIdx.x, wid = tid >> 5, lane = tid & 31;
    int b   = rev ? (BB - 1 - (int)blockIdx.y) : (int)blockIdx.y;
    int chk = rev ? (TBC - 1 - (int)blockIdx.x) : (int)blockIdx.x;
    int n0 = chk * NT;

    const bf16* hHsrc = (dir ? g_hH1 : g_hH0) + ((size_t)b * NN + n0) * 64;
    const bf16* hLsrc = (dir ? g_hL1 : g_hL0) + ((size_t)b * NN + n0) * 64;
    bf16* hHdst = (dir ? g_hH0 : g_hH1) + ((size_t)b * NN + n0) * 64;
    bf16* hLdst = (dir ? g_hL0 : g_hL1) + ((size_t)b * NN + n0) * 64;

    // ---- group A: h tiles + conv weights (needed first) ---------------------
    for (int i = tid; i < 1024; i += 256) {
        int r = i >> 3, q = i & 7;
        uint32_t so = SWZ(r * 128 + q * 16);
        cpa16(sb + MM_HH + so, (const uint4*)(hHsrc + (size_t)r * 64) + q);
        cpa16(sb + MM_HL + so, (const uint4*)(hLsrc + (size_t)r * 64) + q);
    }
    for (int i = tid; i < 512; i += 256) {
        int r = i >> 3, q = i & 7;
        uint32_t so = SWZ(r * 128 + q * 16);
        cpa16(sb + MM_WH + so, (const uint4*)(g_cwH + (size_t)(layer * 64 + r) * 64) + q);
        cpa16(sb + MM_WL + so, (const uint4*)(g_cwL + (size_t)(layer * 64 + r) * 64) + q);
    }
    CPA_COMMIT();
    // ---- group B: G + DFT basis (needed for synthesis/DFT) ------------------
    for (int i = tid; i < 512; i += 256) {
        int r = i >> 3, q = i & 7;
        uint32_t so = SWZ(r * 128 + q * 16);
        cpa16(sb + MM_G + so, (const uint4*)(g_GpP + ((size_t)b * 64 + r) * 64) + q);
        int half = i >> 8, rest = i & 255, j = rest >> 3, qq = rest & 7;
        uint32_t so2 = half * 4096 + SWZ(j * 128 + qq * 16);
        cpa16(sb + MM_BDH + so2, (const uint4*)(g_basDH + (size_t)j * NN + n0 + half * 64) + qq);
        cpa16(sb + MM_BDL + so2, (const uint4*)(g_basDL + (size_t)j * NN + n0 + half * 64) + qq);
    }
    CPA_COMMIT();
    if (tid < 64) ((float*)(smc + MM_CB))[tid] = cb_all[layer * 64 + tid];
    CPA_WAIT(1);
    __syncthreads();

    int lr = lane & 7, li = lane >> 3;
    int drA = (li & 1) * 8, dcA = (li >> 1) * 16;
    int drB = (li >> 1) * 8, dcB = (li & 1) * 16;
    int rA0 = 16 * wid;

    float acc[8][4];
#pragma unroll
    for (int nt = 0; nt < 8; nt++)
#pragma unroll
        for (int k = 0; k < 4; k++) acc[nt][k] = 0.0f;

    // conv: (Hh+Hl)(Wh+Wl) 3-term — runs while group B is still in flight
#pragma unroll
    for (int s = 0; s < 4; s++) {
        int kb = s * 32;
        uint32_t ah[4], al[4];
        ldsm4(sb + MM_HH + SWZ((rA0 + drA + lr) * 128 + kb + dcA), ah);
        ldsm4(sb + MM_HL + SWZ((rA0 + drA + lr) * 128 + kb + dcA), al);
#pragma unroll
        for (int np = 0; np < 4; np++) {
            uint32_t bb[4];
            ldsm4(sb + MM_WH + SWZ((np * 16 + drB + lr) * 128 + kb + dcB), bb);
            mma16816(acc[2 * np],     ah, bb);
            mma16816(acc[2 * np + 1], ah, bb + 2);
            mma16816(acc[2 * np],     al, bb);
            mma16816(acc[2 * np + 1], al, bb + 2);
            ldsm4(sb + MM_WL + SWZ((np * 16 + drB + lr) * 128 + kb + dcB), bb);
            mma16816(acc[2 * np],     ah, bb);
            mma16816(acc[2 * np + 1], ah, bb + 2);
        }
    }
    CPA_WAIT(0);
    __syncthreads();

    // synthesis: A = trans(basD half tile), B = packed G
    {
        int halfS = rA0 >> 6;
        int colA = (rA0 & 63) * 2 + (li & 1) * 16;
        int rowA = (li >> 1) * 8 + lr;
#pragma unroll
        for (int s = 0; s < 2; s++) {
            int kb = s * 32;
            uint32_t ah[4], al[4];
            ldsm4t(sb + MM_BDH + halfS * 4096 + SWZ((s * 16 + rowA) * 128 + colA), ah);
            ldsm4t(sb + MM_BDL + halfS * 4096 + SWZ((s * 16 + rowA) * 128 + colA), al);
#pragma unroll
            for (int np = 0; np < 4; np++) {
                uint32_t bb[4];
                ldsm4(sb + MM_G + SWZ((np * 16 + drB + lr) * 128 + kb + dcB), bb);
                mma16816(acc[2 * np],     ah, bb);
                mma16816(acc[2 * np + 1], ah, bb + 2);
                mma16816(acc[2 * np],     al, bb);
                mma16816(acc[2 * np + 1], al, bb + 2);
                ldsm4(sb + MM_G + SWZ((np * 16 + drB + lr) * 128 + 64 + kb + dcB), bb);
                mma16816(acc[2 * np],     ah, bb);
                mma16816(acc[2 * np + 1], ah, bb + 2);
            }
        }
    }
    __syncthreads();

    // epilogue: bias + gelu, write vH/vL into HH/HL
    int q = lane & 3, g = lane >> 2;
    const float* cbs = (const float*)(smc + MM_CB);
#pragma unroll
    for (int nt = 0; nt < 8; nt++) {
        int o0 = nt * 8 + 2 * q;
        int r0 = 16 * wid + g;
        float v0 = acc[nt][0] + cbs[o0];
        float v1 = acc[nt][1] + cbs[o0 + 1];
        float v2 = acc[nt][2] + cbs[o0];
        float v3 = acc[nt][3] + cbs[o0 + 1];
        if (GELU) {
            v0 = gelu_exact(v0); v1 = gelu_exact(v1);
            v2 = gelu_exact(v2); v3 = gelu_exact(v3);
        }
        bf16 h0, l0, h1, l1;
        split_bf(v0, h0, l0); split_bf(v1, h1, l1);
        *(uint32_t*)(smc + MM_HH + SWZ(r0 * 128 + o0 * 2)) = pack_bf(h0, h1);
        *(uint32_t*)(smc + MM_HL + SWZ(r0 * 128 + o0 * 2)) = pack_bf(l0, l1);
        split_bf(v2, h0, l0); split_bf(v3, h1, l1);
        *(uint32_t*)(smc + MM_HH + SWZ((r0 + 8) * 128 + o0 * 2)) = pack_bf(h0, h1);
        *(uint32_t*)(smc + MM_HL + SWZ((r0 + 8) * 128 + o0 * 2)) = pack_bf(l0, l1);
    }
    __syncthreads();

    for (int i = tid; i < 1024; i += 256) {
        int r = i >> 3, qq = i & 7;
        uint32_t so = SWZ(r * 128 + qq * 16);
        ((uint4*)(hHdst + (size_t)r * 64))[qq] = *(uint4*)(smc + MM_HH + so);
        ((uint4*)(hLdst + (size_t)r * 64))[qq] = *(uint4*)(smc + MM_HL + so);
    }
    if (DFT) {
        dft_core8(sb, MM_HH, MM_HL, MM_BDH, MM_BDL, wid, lane,
                  ((size_t)b * TBC + chk) * J2);
    }
}

// ---------------- fc1 + gelu + fc2 via MMA -----------------------------------
#define FC_HH 0
#define FC_HL 16384
#define FC_WH 32768
#define FC_WL 49152
#define FC_B1 65536
#define FC_W2 66048
#define FC_SZ 66560

__global__ __launch_bounds__(256, 3)
void fc12_kernel(const float* __restrict__ b1, const float* __restrict__ w2,
                 const float* __restrict__ b2, float* __restrict__ out) {
    extern __shared__ char smc[];
    uint32_t sb = smem_u32(smc);
    int tid = threadIdx.x, wid = tid >> 5, lane = tid & 31;
    int b = BB - 1 - (int)blockIdx.y;
    int n0 = (TBC - 1 - (int)blockIdx.x) * NT;

    const bf16* hH = g_hH0 + ((size_t)b * NN + n0) * 64;
    const bf16* hL = g_hL0 + ((size_t)b * NN + n0) * 64;
    for (int i = tid; i < 1024; i += 256) {
        int r = i >> 3, q = i & 7;
        uint32_t so = SWZ(r * 128 + q * 16);
        cpa16(sb + FC_HH + so, (const uint4*)(hH + (size_t)r * 64) + q);
        cpa16(sb + FC_HL + so, (const uint4*)(hL + (size_t)r * 64) + q);
        cpa16(sb + FC_WH + so, (const uint4*)(g_w1TH + (size_t)r * 64) + q);
        cpa16(sb + FC_WL + so, (const uint4*)(g_w1TL + (size_t)r * 64) + q);
    }
    CPA_COMMIT();
    if (tid < 128) {
        ((float*)(smc + FC_B1))[tid] = b1[tid];
        ((float*)(smc + FC_W2))[tid] = w2[tid];
    }
    CPA_WAIT(0);
    __syncthreads();

    int lr = lane & 7, li = lane >> 3;
    int drA = (li & 1) * 8, dcA = (li >> 1) * 16;
    int drB = (li >> 1) * 8, dcB = (li & 1) * 16;
    int rA0 = 16 * wid;

    float acc[16][4];
#pragma unroll
    for (int nt = 0; nt < 16; nt++)
#pragma unroll
        for (int k = 0; k < 4; k++) acc[nt][k] = 0.0f;

#pragma unroll
    for (int s = 0; s < 4; s++) {
        int kb = s * 32;
        uint32_t ah[4], al[4];
        ldsm4(sb + FC_HH + SWZ((rA0 + drA + lr) * 128 + kb + dcA), ah);
        ldsm4(sb + FC_HL + SWZ((rA0 + drA + lr) * 128 + kb + dcA), al);
#pragma unroll
        for (int np = 0; np < 8; np++) {
            uint32_t bb[4];
            ldsm4(sb + FC_WH + SWZ((np * 16 + drB + lr) * 128 + kb + dcB), bb);
            mma16816(acc[2 * np],     ah, bb);
            mma16816(acc[2 * np + 1], ah, bb + 2);
            mma16816(acc[2 * np],     al, bb);
            mma16816(acc[2 * np + 1], al, bb + 2);
            ldsm4(sb + FC_WL + SWZ((np * 16 + drB + lr) * 128 + kb + dcB), bb);
            mma16816(acc[2 * np],     ah, bb);
            mma16816(acc[2 * np + 1], ah, bb + 2);
        }
    }

    int q = lane & 3, g = lane >> 2;
    const float* b1s = (const float*)(smc + FC_B1);
    const float* w2s = (const float*)(smc + FC_W2);
    float s0 = 0.0f, s1 = 0.0f;
#pragma unroll
    for (int nt = 0; nt < 16; nt++) {
        int j0 = nt * 8 + 2 * q;
        s0 = fmaf(w2s[j0],     gelu_exact(acc[nt][0] + b1s[j0]),     s0);
        s0 = fmaf(w2s[j0 + 1], gelu_exact(acc[nt][1] + b1s[j0 + 1]), s0);
        s1 = fmaf(w2s[j0],     gelu_exact(acc[nt][2] + b1s[j0]),     s1);
        s1 = fmaf(w2s[j0 + 1], gelu_exact(acc[nt][3] + b1s[j0 + 1]), s1);
    }
    s0 += __shfl_xor_sync(0xffffffffu, s0, 1);
    s0 += __shfl_xor_sync(0xffffffffu, s0, 2);
    s1 += __shfl_xor_sync(0xffffffffu, s1, 1);
    s1 += __shfl_xor_sync(0xffffffffu, s1, 2);
    if (q == 0) {
        float bv = b2[0];
        out[(size_t)b * NN + n0 + 16 * wid + g]     = s0 + bv;
        out[(size_t)b * NN + n0 + 16 * wid + g + 8] = s1 + bv;
    }
}

// ---------------- host launcher ----------------------------------------------
extern "C" void kernel_launch(void* const* d_in, const int* in_sizes, int n_in,
                              void* d_out, int out_size) {
    const float* x    = (const float*)d_in[0];
    const float* t    = (const float*)d_in[1];
    const float* fc0w = (const float*)d_in[2];
    const float* fc0b = (const float*)d_in[3];
    const float* swr  = (const float*)d_in[4];
    const float* swi  = (const float*)d_in[5];
    const float* cw   = (const float*)d_in[6];
    const float* cb   = (const float*)d_in[7];
    const float* w1   = (const float*)d_in[8];
    const float* b1   = (const float*)d_in[9];
    const float* w2   = (const float*)d_in[10];
    const float* b2   = (const float*)d_in[11];
    float* out = (float*)d_out;

    cudaFuncSetAttribute(mma_layer<true,  true >, cudaFuncAttributeMaxDynamicSharedMemorySize, MM_SZ);
    cudaFuncSetAttribute(mma_layer<false, false>, cudaFuncAttributeMaxDynamicSharedMemorySize, MM_SZ);
    cudaFuncSetAttribute(fc0dft_kernel, cudaFuncAttributeMaxDynamicSharedMemorySize, F0_SZ);
    cudaFuncSetAttribute(fc12_kernel, cudaFuncAttributeMaxDynamicSharedMemorySize, FC_SZ);

    dim3 g(TBC, BB);
    dim3 gr(BB, 8);
    prep_basis<<<NN / 256, 256>>>();
    prep_w<<<(4 * 4096 + 128 * 64 + 255) / 256, 256>>>(cw, w1);

    fc0dft_kernel<<<g, 256, F0_SZ>>>(x, t, fc0w, fc0b);   // forward

    const size_t SWL = (size_t)64 * 64 * 16;
    reduce_kernel<<<gr, 256>>>();
    modemix_kernel<<<BB, 1024>>>(swr + 0 * SWL, swi + 0 * SWL);
    mma_layer<true, true><<<g, 256, MM_SZ>>>(0, 0, 1, cb);   // reversed

    reduce_kernel<<<gr, 256>>>();
    modemix_kernel<<<BB, 1024>>>(swr + 1 * SWL, swi + 1 * SWL);
    mma_layer<true, true><<<g, 256, MM_SZ>>>(1, 1, 0, cb);   // forward

    reduce_kernel<<<gr, 256>>>();
    modemix_kernel<<<BB, 1024>>>(swr + 2 * SWL, swi + 2 * SWL);
    mma_layer<true, true><<<g, 256, MM_SZ>>>(0, 2, 1, cb);   // reversed

    reduce_kernel<<<gr, 256>>>();
    modemix_kernel<<<BB, 1024>>>(swr + 3 * SWL, swi + 3 * SWL);
    mma_layer<false, false><<<g, 256, MM_SZ>>>(1, 3, 0, cb); // forward

    fc12_kernel<<<g, 256, FC_SZ>>>(b1, w2, b2, out);         // reversed
}